// round 2
// baseline (speedup 1.0000x reference)
#include <cuda_runtime.h>
#include <math.h>

#define H        128
#define NC       10
#define NATT     3
#define B_TOTAL  16384
#define M_ROWS   128           // rows per block
#define THREADS  512
#define SSTR     132           // smem row stride (floats), 132 = 128+4, /4 aligned
#define KT       12            // Taylor terms for exp on (-1,1)
#define EPS_LN   1e-5f

// ---------------------------------------------------------------------------
// Register-tiled block GEMM: Out[r][c] = In[r][:] @ Wm[:][c] + bias[c]
// In/Out are [M_ROWS][SSTR] smem tiles, Wm is [H][H] smem row-major.
// Thread (rg, cg) computes a 4-row x 8-col tile.
// ---------------------------------------------------------------------------
__device__ __forceinline__ void block_gemm(const float* __restrict__ In,
                                           const float* __restrict__ Wm,
                                           const float* __restrict__ bias,
                                           float* __restrict__ Out,
                                           int r0, int c0, bool do_tanh)
{
    float acc[4][8];
#pragma unroll
    for (int i = 0; i < 4; i++)
#pragma unroll
        for (int j = 0; j < 8; j++) acc[i][j] = 0.f;

#pragma unroll 8
    for (int k = 0; k < H; k++) {
        float a0 = In[(r0 + 0) * SSTR + k];
        float a1 = In[(r0 + 1) * SSTR + k];
        float a2 = In[(r0 + 2) * SSTR + k];
        float a3 = In[(r0 + 3) * SSTR + k];
        float4 w0 = *(const float4*)&Wm[k * H + c0];
        float4 w1 = *(const float4*)&Wm[k * H + c0 + 4];
        float w[8] = {w0.x, w0.y, w0.z, w0.w, w1.x, w1.y, w1.z, w1.w};
#pragma unroll
        for (int j = 0; j < 8; j++) {
            acc[0][j] = fmaf(a0, w[j], acc[0][j]);
            acc[1][j] = fmaf(a1, w[j], acc[1][j]);
            acc[2][j] = fmaf(a2, w[j], acc[2][j]);
            acc[3][j] = fmaf(a3, w[j], acc[3][j]);
        }
    }
#pragma unroll
    for (int i = 0; i < 4; i++) {
#pragma unroll
        for (int j = 0; j < 8; j++) {
            float v = acc[i][j] + bias[c0 + j];
            if (do_tanh) v = tanhf(v);
            Out[(r0 + i) * SSTR + c0 + j] = v;
        }
    }
}

__global__ void __launch_bounds__(THREADS, 1)
simple_attention_kernel(const float* __restrict__ x,
                        const float* __restrict__ W_in,
                        const float* __restrict__ b_in,
                        const float* __restrict__ W_att,
                        const float* __restrict__ b_att,
                        const float* __restrict__ gamma,
                        const float* __restrict__ beta,
                        const float* __restrict__ W_c,
                        const float* __restrict__ b_c,
                        float* __restrict__ out)
{
    extern __shared__ float smem[];
    float* sW  = smem;                    // H*H = 16384 floats (64 KB)
    float* sH  = sW + H * H;              // M_ROWS*SSTR
    float* sU  = sH + M_ROWS * SSTR;      // M_ROWS*SSTR
    float* sB  = sU + M_ROWS * SSTR;      // H
    float* sG  = sB + H;                  // H
    float* sBe = sG + H;                  // H

    const int tid  = threadIdx.x;
    const int base = blockIdx.x * M_ROWS;

    // GEMM mapping: 4 rows x 8 cols per thread
    const int cg = tid & 15;
    const int rg = tid >> 4;
    const int r0 = rg * 4, c0 = cg * 8;

    // Row mapping for moments/softmax/LN: 4 consecutive lanes per row,
    // lane pp owns columns j with j % 4 == pp (conflict-free with SSTR=132).
    const int rr = tid >> 2;
    const int pp = tid & 3;

    // Taylor coefficients 1/k!
    const float invf[KT] = {
        1.0f, 1.0f, 0.5f, 1.6666666667e-1f, 4.1666666667e-2f,
        8.3333333333e-3f, 1.3888888889e-3f, 1.9841269841e-4f,
        2.4801587302e-5f, 2.7557319224e-6f, 2.7557319224e-7f,
        2.5052108385e-8f};

    // ---- Stage x -> sU, W_in -> sW, b_in -> sB ----
    {
        const float4* xg = (const float4*)(x + (size_t)base * H);
#pragma unroll
        for (int it = 0; it < (M_ROWS * H / 4) / THREADS; it++) {
            int i   = tid + it * THREADS;
            int row = i >> 5;          // 32 float4 per row
            int c4  = i & 31;
            *(float4*)&sU[row * SSTR + c4 * 4] = xg[i];
        }
        const float4* wg  = (const float4*)W_in;
        float4*       sW4 = (float4*)sW;
#pragma unroll
        for (int it = 0; it < (H * H / 4) / THREADS; it++)
            sW4[tid + it * THREADS] = wg[tid + it * THREADS];
        if (tid < H) sB[tid] = b_in[tid];
    }
    __syncthreads();

    // ---- in_proj: sH = x @ W_in + b_in ----
    block_gemm(sU, sW, sB, sH, r0, c0, false);
    __syncthreads();

    // ---- attention layers ----
    for (int l = 0; l < NATT; l++) {
        // stage layer weights
        {
            const float4* wg  = (const float4*)(W_att + (size_t)l * H * H);
            float4*       sW4 = (float4*)sW;
#pragma unroll
            for (int it = 0; it < (H * H / 4) / THREADS; it++)
                sW4[tid + it * THREADS] = wg[tid + it * THREADS];
            if (tid < H) {
                sB[tid]  = b_att[l * H + tid];
                sG[tid]  = gamma[l * H + tid];
                sBe[tid] = beta[l * H + tid];
            }
        }
        __syncthreads();

        // u = tanh(h @ W + b) -> sU
        block_gemm(sH, sW, sB, sU, r0, c0, true);
        __syncthreads();

        // ---- Taylor moments: s_k = sum_j u_j^k, m_k = sum_j u_j^k h_j ----
        float sm[KT], mm[KT];
#pragma unroll
        for (int k = 0; k < KT; k++) { sm[k] = 0.f; mm[k] = 0.f; }

#pragma unroll 4
        for (int jj = 0; jj < 32; jj++) {
            int   j  = 4 * jj + pp;
            float u  = sU[rr * SSTR + j];
            float hv = sH[rr * SSTR + j];
            float pw = 1.f;
#pragma unroll
            for (int k = 0; k < KT; k++) {
                sm[k] += pw;
                mm[k] = fmaf(pw, hv, mm[k]);
                pw *= u;
            }
        }
        // reduce across the 4 lanes of this row, fold 1/k!
#pragma unroll
        for (int k = 0; k < KT; k++) {
            sm[k] += __shfl_xor_sync(0xffffffffu, sm[k], 1);
            sm[k] += __shfl_xor_sync(0xffffffffu, sm[k], 2);
            mm[k] += __shfl_xor_sync(0xffffffffu, mm[k], 1);
            mm[k] += __shfl_xor_sync(0xffffffffu, mm[k], 2);
            sm[k] *= invf[k];
            mm[k] *= invf[k];
        }

        // ---- out_i = P_m(u_i)/P_s(u_i);  z = h + out -> sU; stats ----
        float lsum = 0.f, lsq = 0.f;
#pragma unroll 4
        for (int jj = 0; jj < 32; jj++) {
            int   j   = 4 * jj + pp;
            float u   = sU[rr * SSTR + j];
            float num = mm[KT - 1], den = sm[KT - 1];
#pragma unroll
            for (int k = KT - 2; k >= 0; k--) {
                num = fmaf(num, u, mm[k]);
                den = fmaf(den, u, sm[k]);
            }
            float o = __fdividef(num, den);
            float z = sH[rr * SSTR + j] + o;
            sU[rr * SSTR + j] = z;          // stash z (own slots only)
            lsum += z;
            lsq  = fmaf(z, z, lsq);
        }
        lsum += __shfl_xor_sync(0xffffffffu, lsum, 1);
        lsum += __shfl_xor_sync(0xffffffffu, lsum, 2);
        lsq  += __shfl_xor_sync(0xffffffffu, lsq, 1);
        lsq  += __shfl_xor_sync(0xffffffffu, lsq, 2);

        float mu   = lsum * (1.f / H);
        float var  = lsq * (1.f / H) - mu * mu;
        float rinv = rsqrtf(var + EPS_LN);

        // ---- LayerNorm -> sH ----
#pragma unroll 4
        for (int jj = 0; jj < 32; jj++) {
            int   j = 4 * jj + pp;
            float z = sU[rr * SSTR + j];
            sH[rr * SSTR + j] = fmaf((z - mu) * rinv, sG[j], sBe[j]);
        }
        __syncthreads();
    }

    // ---- classifier: out = h @ W_c + b_c ----
    {
        for (int i = tid; i < H * NC; i += THREADS) sW[i] = W_c[i];
        if (tid < NC) sB[tid] = b_c[tid];
    }
    __syncthreads();

    {
        float acc[NC];
#pragma unroll
        for (int c = 0; c < NC; c++) acc[c] = 0.f;
#pragma unroll 4
        for (int jj = 0; jj < 32; jj++) {
            int   j  = 4 * jj + pp;
            float hv = sH[rr * SSTR + j];
#pragma unroll
            for (int c = 0; c < NC; c++)
                acc[c] = fmaf(hv, sW[j * NC + c], acc[c]);
        }
#pragma unroll
        for (int c = 0; c < NC; c++) {
            acc[c] += __shfl_xor_sync(0xffffffffu, acc[c], 1);
            acc[c] += __shfl_xor_sync(0xffffffffu, acc[c], 2);
        }
        if (pp == 0) {
#pragma unroll
            for (int c = 0; c < NC; c++)
                out[(size_t)(base + rr) * NC + c] = acc[c] + sB[c];
        }
    }
}

extern "C" void kernel_launch(void* const* d_in, const int* in_sizes, int n_in,
                              void* d_out, int out_size)
{
    const float* x     = (const float*)d_in[0];
    const float* W_in  = (const float*)d_in[1];
    const float* b_in  = (const float*)d_in[2];
    const float* W_att = (const float*)d_in[3];
    const float* b_att = (const float*)d_in[4];
    const float* gam   = (const float*)d_in[5];
    const float* bet   = (const float*)d_in[6];
    const float* W_c   = (const float*)d_in[7];
    const float* b_c   = (const float*)d_in[8];

    size_t smem_bytes = (size_t)(H * H + 2 * M_ROWS * SSTR + 3 * H) * sizeof(float);
    cudaFuncSetAttribute(simple_attention_kernel,
                         cudaFuncAttributeMaxDynamicSharedMemorySize,
                         (int)smem_bytes);

    int nblocks = B_TOTAL / M_ROWS;   // 128
    simple_attention_kernel<<<nblocks, THREADS, smem_bytes>>>(
        x, W_in, b_in, W_att, b_att, gam, bet, W_c, b_c, (float*)d_out);
}

// round 3
// speedup vs baseline: 1.2756x; 1.2756x over previous
#include <cuda_runtime.h>
#include <math.h>

#define H        128
#define NC       10
#define NATT     3
#define B_TOTAL  16384
#define M_ROWS   128           // rows per block
#define THREADS  512
#define SSTR     132           // smem row stride (floats); 132*4B is 16B-aligned
#define KT       10            // Taylor terms for exp on (-1,1): remainder <= e/10! ~ 7.5e-7
#define EPS_LN   1e-5f

// fast accurate tanh: 1 - 2/(exp(2x)+1); saturates correctly at +/-inf
__device__ __forceinline__ float fast_tanh(float x)
{
    return 1.0f - 2.0f * __fdividef(1.0f, __expf(2.0f * x) + 1.0f);
}

// ---------------------------------------------------------------------------
// Register-tiled block GEMM: Out[r][c] = In[r][:] @ Wm[:][c] + bias[c]
// In/Out: [M_ROWS][SSTR] smem tiles. Wm: [H][H] smem row-major.
// Thread (rg, cg): rows r0..r0+3, cols {4cg..4cg+3} and {64+4cg..64+4cg+3}.
// All LDS are conflict-free: W quarters hit banks 0..31 exactly, A is broadcast.
// ---------------------------------------------------------------------------
__device__ __forceinline__ void block_gemm(const float* __restrict__ In,
                                           const float* __restrict__ Wm,
                                           const float* __restrict__ bias,
                                           float* __restrict__ Out,
                                           int r0, int cA, int cB, bool do_tanh)
{
    float acc[4][8];
#pragma unroll
    for (int i = 0; i < 4; i++)
#pragma unroll
        for (int j = 0; j < 8; j++) acc[i][j] = 0.f;

#pragma unroll 4
    for (int k4 = 0; k4 < H; k4 += 4) {
        float4 a0 = *(const float4*)&In[(r0 + 0) * SSTR + k4];
        float4 a1 = *(const float4*)&In[(r0 + 1) * SSTR + k4];
        float4 a2 = *(const float4*)&In[(r0 + 2) * SSTR + k4];
        float4 a3 = *(const float4*)&In[(r0 + 3) * SSTR + k4];
        float av0[4] = {a0.x, a0.y, a0.z, a0.w};
        float av1[4] = {a1.x, a1.y, a1.z, a1.w};
        float av2[4] = {a2.x, a2.y, a2.z, a2.w};
        float av3[4] = {a3.x, a3.y, a3.z, a3.w};
#pragma unroll
        for (int kk = 0; kk < 4; kk++) {
            float4 wA = *(const float4*)&Wm[(k4 + kk) * H + cA];
            float4 wB = *(const float4*)&Wm[(k4 + kk) * H + cB];
            float w[8] = {wA.x, wA.y, wA.z, wA.w, wB.x, wB.y, wB.z, wB.w};
#pragma unroll
            for (int j = 0; j < 8; j++) {
                acc[0][j] = fmaf(av0[kk], w[j], acc[0][j]);
                acc[1][j] = fmaf(av1[kk], w[j], acc[1][j]);
                acc[2][j] = fmaf(av2[kk], w[j], acc[2][j]);
                acc[3][j] = fmaf(av3[kk], w[j], acc[3][j]);
            }
        }
    }

    float4 bA = *(const float4*)&bias[cA];
    float4 bB = *(const float4*)&bias[cB];
    float bb[8] = {bA.x, bA.y, bA.z, bA.w, bB.x, bB.y, bB.z, bB.w};
#pragma unroll
    for (int i = 0; i < 4; i++) {
        float v[8];
#pragma unroll
        for (int j = 0; j < 8; j++) {
            v[j] = acc[i][j] + bb[j];
            if (do_tanh) v[j] = fast_tanh(v[j]);
        }
        *(float4*)&Out[(r0 + i) * SSTR + cA] = make_float4(v[0], v[1], v[2], v[3]);
        *(float4*)&Out[(r0 + i) * SSTR + cB] = make_float4(v[4], v[5], v[6], v[7]);
    }
}

__global__ void __launch_bounds__(THREADS, 1)
simple_attention_kernel(const float* __restrict__ x,
                        const float* __restrict__ W_in,
                        const float* __restrict__ b_in,
                        const float* __restrict__ W_att,
                        const float* __restrict__ b_att,
                        const float* __restrict__ gamma,
                        const float* __restrict__ beta,
                        const float* __restrict__ W_c,
                        const float* __restrict__ b_c,
                        float* __restrict__ out)
{
    extern __shared__ float smem[];
    float* sW  = smem;                    // H*H floats (64 KB)
    float* sH  = sW + H * H;              // M_ROWS*SSTR
    float* sU  = sH + M_ROWS * SSTR;      // M_ROWS*SSTR
    float* sB  = sU + M_ROWS * SSTR;      // H
    float* sG  = sB + H;                  // H
    float* sBe = sG + H;                  // H

    const int tid  = threadIdx.x;
    const int base = blockIdx.x * M_ROWS;

    // GEMM mapping: 4 rows x (4+4 split) cols per thread
    const int cg = tid & 15;
    const int rg = tid >> 4;
    const int r0 = rg * 4;
    const int cA = cg * 4;
    const int cB = 64 + cg * 4;

    // Row mapping for moments/softmax/LN: 4 lanes per row, lane pp owns j%4==pp
    const int rr = tid >> 2;
    const int pp = tid & 3;

    // 1/k!
    const float invf[KT] = {
        1.0f, 1.0f, 0.5f, 1.6666666667e-1f, 4.1666666667e-2f,
        8.3333333333e-3f, 1.3888888889e-3f, 1.9841269841e-4f,
        2.4801587302e-5f, 2.7557319224e-6f};

    // ---- Stage x -> sU, W_in -> sW, b_in -> sB ----
    {
        const float4* xg = (const float4*)(x + (size_t)base * H);
#pragma unroll
        for (int it = 0; it < (M_ROWS * H / 4) / THREADS; it++) {
            int i   = tid + it * THREADS;
            int row = i >> 5;          // 32 float4 per row
            int c4  = i & 31;
            *(float4*)&sU[row * SSTR + c4 * 4] = xg[i];
        }
        const float4* wg  = (const float4*)W_in;
        float4*       sW4 = (float4*)sW;
#pragma unroll
        for (int it = 0; it < (H * H / 4) / THREADS; it++)
            sW4[tid + it * THREADS] = wg[tid + it * THREADS];
        if (tid < H) sB[tid] = b_in[tid];
    }
    __syncthreads();

    // ---- in_proj: sH = x @ W_in + b_in ----
    block_gemm(sU, sW, sB, sH, r0, cA, cB, false);
    __syncthreads();

    // ---- attention layers ----
    for (int l = 0; l < NATT; l++) {
        // stage layer weights
        {
            const float4* wg  = (const float4*)(W_att + (size_t)l * H * H);
            float4*       sW4 = (float4*)sW;
#pragma unroll
            for (int it = 0; it < (H * H / 4) / THREADS; it++)
                sW4[tid + it * THREADS] = wg[tid + it * THREADS];
            if (tid < H) {
                sB[tid]  = b_att[l * H + tid];
                sG[tid]  = gamma[l * H + tid];
                sBe[tid] = beta[l * H + tid];
            }
        }
        __syncthreads();

        // u = tanh(h @ W + b) -> sU
        block_gemm(sH, sW, sB, sU, r0, cA, cB, true);
        __syncthreads();

        // ---- Taylor moments: s_k = sum_j u^k, m_k = sum_j u^k h_j ----
        float sm[KT], mm[KT];
#pragma unroll
        for (int k = 0; k < KT; k++) { sm[k] = 0.f; mm[k] = 0.f; }

#pragma unroll 4
        for (int jj = 0; jj < 32; jj++) {
            int   j  = 4 * jj + pp;
            float u  = sU[rr * SSTR + j];
            float hv = sH[rr * SSTR + j];
            float pw = 1.f;
#pragma unroll
            for (int k = 0; k < KT; k++) {
                sm[k] += pw;
                mm[k] = fmaf(pw, hv, mm[k]);
                pw *= u;
            }
        }
#pragma unroll
        for (int k = 0; k < KT; k++) {
            sm[k] += __shfl_xor_sync(0xffffffffu, sm[k], 1);
            sm[k] += __shfl_xor_sync(0xffffffffu, sm[k], 2);
            mm[k] += __shfl_xor_sync(0xffffffffu, mm[k], 1);
            mm[k] += __shfl_xor_sync(0xffffffffu, mm[k], 2);
            sm[k] *= invf[k];
            mm[k] *= invf[k];
        }

        // ---- out_i = P_m(u_i)/P_s(u_i);  z = h + out -> sU; stats ----
        float lsum = 0.f, lsq = 0.f;
#pragma unroll 4
        for (int jj = 0; jj < 32; jj++) {
            int   j   = 4 * jj + pp;
            float u   = sU[rr * SSTR + j];
            float num = mm[KT - 1], den = sm[KT - 1];
#pragma unroll
            for (int k = KT - 2; k >= 0; k--) {
                num = fmaf(num, u, mm[k]);
                den = fmaf(den, u, sm[k]);
            }
            float o = __fdividef(num, den);
            float z = sH[rr * SSTR + j] + o;
            sU[rr * SSTR + j] = z;          // stash z (own slots only)
            lsum += z;
            lsq  = fmaf(z, z, lsq);
        }
        lsum += __shfl_xor_sync(0xffffffffu, lsum, 1);
        lsum += __shfl_xor_sync(0xffffffffu, lsum, 2);
        lsq  += __shfl_xor_sync(0xffffffffu, lsq, 1);
        lsq  += __shfl_xor_sync(0xffffffffu, lsq, 2);

        float mu   = lsum * (1.f / H);
        float var  = lsq * (1.f / H) - mu * mu;
        float rinv = rsqrtf(var + EPS_LN);

        // ---- LayerNorm -> sH ----
#pragma unroll 4
        for (int jj = 0; jj < 32; jj++) {
            int   j = 4 * jj + pp;
            float z = sU[rr * SSTR + j];
            sH[rr * SSTR + j] = fmaf((z - mu) * rinv, sG[j], sBe[j]);
        }
        __syncthreads();
    }

    // ---- classifier: out = h @ W_c + b_c ----
    {
        for (int i = tid; i < H * NC; i += THREADS) sW[i] = W_c[i];
        if (tid < NC) sB[tid] = b_c[tid];
    }
    __syncthreads();

    {
        float acc[NC];
#pragma unroll
        for (int c = 0; c < NC; c++) acc[c] = 0.f;
#pragma unroll 4
        for (int jj = 0; jj < 32; jj++) {
            int   j  = 4 * jj + pp;
            float hv = sH[rr * SSTR + j];
#pragma unroll
            for (int c = 0; c < NC; c++)
                acc[c] = fmaf(hv, sW[j * NC + c], acc[c]);
        }
#pragma unroll
        for (int c = 0; c < NC; c++) {
            acc[c] += __shfl_xor_sync(0xffffffffu, acc[c], 1);
            acc[c] += __shfl_xor_sync(0xffffffffu, acc[c], 2);
        }
        if (pp == 0) {
#pragma unroll
            for (int c = 0; c < NC; c++)
                out[(size_t)(base + rr) * NC + c] = acc[c] + sB[c];
        }
    }
}

extern "C" void kernel_launch(void* const* d_in, const int* in_sizes, int n_in,
                              void* d_out, int out_size)
{
    const float* x     = (const float*)d_in[0];
    const float* W_in  = (const float*)d_in[1];
    const float* b_in  = (const float*)d_in[2];
    const float* W_att = (const float*)d_in[3];
    const float* b_att = (const float*)d_in[4];
    const float* gam   = (const float*)d_in[5];
    const float* bet   = (const float*)d_in[6];
    const float* W_c   = (const float*)d_in[7];
    const float* b_c   = (const float*)d_in[8];

    size_t smem_bytes = (size_t)(H * H + 2 * M_ROWS * SSTR + 3 * H) * sizeof(float);
    cudaFuncSetAttribute(simple_attention_kernel,
                         cudaFuncAttributeMaxDynamicSharedMemorySize,
                         (int)smem_bytes);

    int nblocks = B_TOTAL / M_ROWS;   // 128
    simple_attention_kernel<<<nblocks, THREADS, smem_bytes>>>(
        x, W_in, b_in, W_att, b_att, gam, bet, W_c, b_c, (float*)d_out);
}

// round 6
// speedup vs baseline: 1.3682x; 1.0725x over previous
#include <cuda_runtime.h>
#include <math.h>
#include <stdint.h>

#define H        128
#define NC       10
#define NATT     3
#define B_TOTAL  16384
#define M_ROWS   128           // rows per block
#define THREADS  512
#define SSTR     132           // smem row stride (floats); 16B-aligned
#define KT       10            // Taylor terms; remainder <= e/10! ~ 7.5e-7
#define KT2      (KT / 2)
#define EPS_LN   1e-5f

typedef unsigned long long ull;

// ---------------- packed f32x2 helpers (PTX; base sm_100+ feature) ----------------
__device__ __forceinline__ ull pack2(float lo, float hi) {
    ull r; asm("mov.b64 %0, {%1, %2};" : "=l"(r) : "f"(lo), "f"(hi)); return r;
}
__device__ __forceinline__ void unpack2(ull v, float& lo, float& hi) {
    asm("mov.b64 {%0, %1}, %2;" : "=f"(lo), "=f"(hi) : "l"(v));
}
__device__ __forceinline__ ull fma2(ull a, ull b, ull c) {
    ull d; asm("fma.rn.f32x2 %0, %1, %2, %3;" : "=l"(d) : "l"(a), "l"(b), "l"(c)); return d;
}
__device__ __forceinline__ ull add2(ull a, ull b) {
    ull d; asm("add.rn.f32x2 %0, %1, %2;" : "=l"(d) : "l"(a), "l"(b)); return d;
}
__device__ __forceinline__ ull mul2(ull a, ull b) {
    ull d; asm("mul.rn.f32x2 %0, %1, %2;" : "=l"(d) : "l"(a), "l"(b)); return d;
}

// fast accurate tanh: 1 - 2/(exp(2x)+1)
__device__ __forceinline__ float fast_tanh(float x)
{
    return 1.0f - 2.0f * __fdividef(1.0f, __expf(2.0f * x) + 1.0f);
}

// ---------------------------------------------------------------------------
// Register-tiled block GEMM with packed f32x2 FMA.
// Out[r][c] = In[r][:] @ Wm[:][c] + bias[c]
// Thread (rg, cg): rows r0..r0+3, cols {4cg..4cg+3} and {64+4cg..64+4cg+3}.
// W loaded as ulonglong2 (two f32x2 operands per LDS.128); conflict-free.
// ---------------------------------------------------------------------------
__device__ __forceinline__ void block_gemm(const float* __restrict__ In,
                                           const float* __restrict__ Wm,
                                           const float* __restrict__ bias,
                                           float* __restrict__ Out,
                                           int r0, int cA, int cB, bool do_tanh)
{
    ull acc[4][4];
#pragma unroll
    for (int i = 0; i < 4; i++)
#pragma unroll
        for (int j = 0; j < 4; j++) acc[i][j] = 0ull;

#pragma unroll 4
    for (int k4 = 0; k4 < H; k4 += 4) {
        float4 a0 = *(const float4*)&In[(r0 + 0) * SSTR + k4];
        float4 a1 = *(const float4*)&In[(r0 + 1) * SSTR + k4];
        float4 a2 = *(const float4*)&In[(r0 + 2) * SSTR + k4];
        float4 a3 = *(const float4*)&In[(r0 + 3) * SSTR + k4];
        float av0[4] = {a0.x, a0.y, a0.z, a0.w};
        float av1[4] = {a1.x, a1.y, a1.z, a1.w};
        float av2[4] = {a2.x, a2.y, a2.z, a2.w};
        float av3[4] = {a3.x, a3.y, a3.z, a3.w};
#pragma unroll
        for (int kk = 0; kk < 4; kk++) {
            ulonglong2 wa = *(const ulonglong2*)&Wm[(k4 + kk) * H + cA];
            ulonglong2 wb = *(const ulonglong2*)&Wm[(k4 + kk) * H + cB];
            ull p0 = pack2(av0[kk], av0[kk]);
            ull p1 = pack2(av1[kk], av1[kk]);
            ull p2 = pack2(av2[kk], av2[kk]);
            ull p3 = pack2(av3[kk], av3[kk]);
            acc[0][0] = fma2(p0, wa.x, acc[0][0]);
            acc[0][1] = fma2(p0, wa.y, acc[0][1]);
            acc[0][2] = fma2(p0, wb.x, acc[0][2]);
            acc[0][3] = fma2(p0, wb.y, acc[0][3]);
            acc[1][0] = fma2(p1, wa.x, acc[1][0]);
            acc[1][1] = fma2(p1, wa.y, acc[1][1]);
            acc[1][2] = fma2(p1, wb.x, acc[1][2]);
            acc[1][3] = fma2(p1, wb.y, acc[1][3]);
            acc[2][0] = fma2(p2, wa.x, acc[2][0]);
            acc[2][1] = fma2(p2, wa.y, acc[2][1]);
            acc[2][2] = fma2(p2, wb.x, acc[2][2]);
            acc[2][3] = fma2(p2, wb.y, acc[2][3]);
            acc[3][0] = fma2(p3, wa.x, acc[3][0]);
            acc[3][1] = fma2(p3, wa.y, acc[3][1]);
            acc[3][2] = fma2(p3, wb.x, acc[3][2]);
            acc[3][3] = fma2(p3, wb.y, acc[3][3]);
        }
    }

    ulonglong2 ba = *(const ulonglong2*)&bias[cA];
    ulonglong2 bb = *(const ulonglong2*)&bias[cB];
#pragma unroll
    for (int i = 0; i < 4; i++) {
        ull s0 = add2(acc[i][0], ba.x);
        ull s1 = add2(acc[i][1], ba.y);
        ull s2 = add2(acc[i][2], bb.x);
        ull s3 = add2(acc[i][3], bb.y);
        float v[8];
        unpack2(s0, v[0], v[1]);
        unpack2(s1, v[2], v[3]);
        unpack2(s2, v[4], v[5]);
        unpack2(s3, v[6], v[7]);
        if (do_tanh) {
#pragma unroll
            for (int j = 0; j < 8; j++) v[j] = fast_tanh(v[j]);
        }
        *(float4*)&Out[(r0 + i) * SSTR + cA] = make_float4(v[0], v[1], v[2], v[3]);
        *(float4*)&Out[(r0 + i) * SSTR + cB] = make_float4(v[4], v[5], v[6], v[7]);
    }
}

__global__ void __launch_bounds__(THREADS, 1)
simple_attention_kernel(const float* __restrict__ x,
                        const float* __restrict__ W_in,
                        const float* __restrict__ b_in,
                        const float* __restrict__ W_att,
                        const float* __restrict__ b_att,
                        const float* __restrict__ gamma,
                        const float* __restrict__ beta,
                        const float* __restrict__ W_c,
                        const float* __restrict__ b_c,
                        float* __restrict__ out)
{
    extern __shared__ float smem[];
    float* sW  = smem;                    // H*H floats (64 KB)
    float* sH  = sW + H * H;              // M_ROWS*SSTR
    float* sU  = sH + M_ROWS * SSTR;      // M_ROWS*SSTR
    float* sB  = sU + M_ROWS * SSTR;      // H
    float* sG  = sB + H;                  // H
    float* sBe = sG + H;                  // H

    const int tid  = threadIdx.x;
    const int base = blockIdx.x * M_ROWS;

    // GEMM mapping
    const int cg = tid & 15;
    const int rg = tid >> 4;
    const int r0 = rg * 4;
    const int cA = cg * 4;
    const int cB = 64 + cg * 4;

    // Row mapping for moments/softmax/LN: 4 lanes per row, lane pp owns j%4==pp
    const int rr = tid >> 2;
    const int pp = tid & 3;

    const float invf[KT] = {
        1.0f, 1.0f, 0.5f, 1.6666666667e-1f, 4.1666666667e-2f,
        8.3333333333e-3f, 1.3888888889e-3f, 1.9841269841e-4f,
        2.4801587302e-5f, 2.7557319224e-6f};

    // ---- Stage x -> sU, W_in -> sW, b_in -> sB ----
    {
        const float4* xg = (const float4*)(x + (size_t)base * H);
#pragma unroll
        for (int it = 0; it < (M_ROWS * H / 4) / THREADS; it++) {
            int i   = tid + it * THREADS;
            int row = i >> 5;
            int c4  = i & 31;
            *(float4*)&sU[row * SSTR + c4 * 4] = xg[i];
        }
        const float4* wg  = (const float4*)W_in;
        float4*       sW4 = (float4*)sW;
#pragma unroll
        for (int it = 0; it < (H * H / 4) / THREADS; it++)
            sW4[tid + it * THREADS] = wg[tid + it * THREADS];
        if (tid < H) sB[tid] = b_in[tid];
    }
    __syncthreads();

    // ---- in_proj: sH = x @ W_in + b_in ----
    block_gemm(sU, sW, sB, sH, r0, cA, cB, false);
    __syncthreads();

    // ---- attention layers ----
    for (int l = 0; l < NATT; l++) {
        {
            const float4* wg  = (const float4*)(W_att + (size_t)l * H * H);
            float4*       sW4 = (float4*)sW;
#pragma unroll
            for (int it = 0; it < (H * H / 4) / THREADS; it++)
                sW4[tid + it * THREADS] = wg[tid + it * THREADS];
            if (tid < H) {
                sB[tid]  = b_att[l * H + tid];
                sG[tid]  = gamma[l * H + tid];
                sBe[tid] = beta[l * H + tid];
            }
        }
        __syncthreads();

        // u = tanh(h @ W + b) -> sU
        block_gemm(sH, sW, sB, sU, r0, cA, cB, true);
        __syncthreads();

        // ---- Taylor moments (packed pair-stride recurrence) ----
        // pw_pair = {u^{2p}, u^{2p+1}}; advance by {u^2,u^2}.
        ull sm2[KT2], mm2[KT2];
#pragma unroll
        for (int p = 0; p < KT2; p++) { sm2[p] = 0ull; mm2[p] = 0ull; }

#pragma unroll 4
        for (int jj = 0; jj < 32; jj++) {
            int   j  = 4 * jj + pp;
            float u  = sU[rr * SSTR + j];
            float hv = sH[rr * SSTR + j];
            float uu = u * u;
            ull pwp = pack2(1.0f, u);
            ull u2d = pack2(uu, uu);
            ull hv2 = pack2(hv, hv);
#pragma unroll
            for (int p = 0; p < KT2; p++) {
                sm2[p] = add2(sm2[p], pwp);
                mm2[p] = fma2(pwp, hv2, mm2[p]);
                if (p < KT2 - 1) pwp = mul2(pwp, u2d);
            }
        }
        // unpack, reduce across 4 lanes, fold 1/k!
        float sm[KT], mm[KT];
#pragma unroll
        for (int p = 0; p < KT2; p++) {
            unpack2(sm2[p], sm[2 * p], sm[2 * p + 1]);
            unpack2(mm2[p], mm[2 * p], mm[2 * p + 1]);
        }
#pragma unroll
        for (int k = 0; k < KT; k++) {
            sm[k] += __shfl_xor_sync(0xffffffffu, sm[k], 1);
            sm[k] += __shfl_xor_sync(0xffffffffu, sm[k], 2);
            mm[k] += __shfl_xor_sync(0xffffffffu, mm[k], 1);
            mm[k] += __shfl_xor_sync(0xffffffffu, mm[k], 2);
            sm[k] *= invf[k];
            mm[k] *= invf[k];
        }
        // pre-pack Horner coefficients {num_coef, den_coef}
        ull pm[KT];
#pragma unroll
        for (int k = 0; k < KT; k++) pm[k] = pack2(mm[k], sm[k]);

        // ---- out_i = P_m(u_i)/P_s(u_i);  z = h + out -> sU; LN stats ----
        float lsum = 0.f, lsq = 0.f;
#pragma unroll 4
        for (int jj = 0; jj < 32; jj++) {
            int   j  = 4 * jj + pp;
            float u  = sU[rr * SSTR + j];
            ull   u2 = pack2(u, u);
            ull   nd = pm[KT - 1];
#pragma unroll
            for (int k = KT - 2; k >= 0; k--)
                nd = fma2(nd, u2, pm[k]);
            float num, den;
            unpack2(nd, num, den);
            float o = __fdividef(num, den);
            float z = sH[rr * SSTR + j] + o;
            sU[rr * SSTR + j] = z;
            lsum += z;
            lsq  = fmaf(z, z, lsq);
        }
        lsum += __shfl_xor_sync(0xffffffffu, lsum, 1);
        lsum += __shfl_xor_sync(0xffffffffu, lsum, 2);
        lsq  += __shfl_xor_sync(0xffffffffu, lsq, 1);
        lsq  += __shfl_xor_sync(0xffffffffu, lsq, 2);

        float mu   = lsum * (1.f / H);
        float var  = lsq * (1.f / H) - mu * mu;
        float rinv = rsqrtf(var + EPS_LN);

        // ---- LayerNorm -> sH ----
#pragma unroll 4
        for (int jj = 0; jj < 32; jj++) {
            int   j = 4 * jj + pp;
            float z = sU[rr * SSTR + j];
            sH[rr * SSTR + j] = fmaf((z - mu) * rinv, sG[j], sBe[j]);
        }
        __syncthreads();
    }

    // ---- classifier: out = h @ W_c + b_c ----
    {
        for (int i = tid; i < H * NC; i += THREADS) sW[i] = W_c[i];
        if (tid < NC) sB[tid] = b_c[tid];
    }
    __syncthreads();

    {
        ull acc2[NC / 2];
#pragma unroll
        for (int c = 0; c < NC / 2; c++) acc2[c] = 0ull;
#pragma unroll 4
        for (int jj = 0; jj < 32; jj++) {
            int   j  = 4 * jj + pp;
            float hv = sH[rr * SSTR + j];
            ull hv2 = pack2(hv, hv);
#pragma unroll
            for (int c = 0; c < NC / 2; c++) {
                ull wp = *(const ull*)&sW[j * NC + 2 * c];   // 8B-aligned: j*10+2c even
                acc2[c] = fma2(hv2, wp, acc2[c]);
            }
        }
        float acc[NC];
#pragma unroll
        for (int c = 0; c < NC / 2; c++) unpack2(acc2[c], acc[2 * c], acc[2 * c + 1]);
#pragma unroll
        for (int c = 0; c < NC; c++) {
            acc[c] += __shfl_xor_sync(0xffffffffu, acc[c], 1);
            acc[c] += __shfl_xor_sync(0xffffffffu, acc[c], 2);
        }
        if (pp == 0) {
#pragma unroll
            for (int c = 0; c < NC; c++)
                out[(size_t)(base + rr) * NC + c] = acc[c] + sB[c];
        }
    }
}

extern "C" void kernel_launch(void* const* d_in, const int* in_sizes, int n_in,
                              void* d_out, int out_size)
{
    const float* x     = (const float*)d_in[0];
    const float* W_in  = (const float*)d_in[1];
    const float* b_in  = (const float*)d_in[2];
    const float* W_att = (const float*)d_in[3];
    const float* b_att = (const float*)d_in[4];
    const float* gam   = (const float*)d_in[5];
    const float* bet   = (const float*)d_in[6];
    const float* W_c   = (const float*)d_in[7];
    const float* b_c   = (const float*)d_in[8];

    size_t smem_bytes = (size_t)(H * H + 2 * M_ROWS * SSTR + 3 * H) * sizeof(float);
    cudaFuncSetAttribute(simple_attention_kernel,
                         cudaFuncAttributeMaxDynamicSharedMemorySize,
                         (int)smem_bytes);

    int nblocks = B_TOTAL / M_ROWS;   // 128
    simple_attention_kernel<<<nblocks, THREADS, smem_bytes>>>(
        x, W_in, b_in, W_att, b_att, gam, bet, W_c, b_c, (float*)d_out);
}

// round 9
// speedup vs baseline: 1.4795x; 1.0814x over previous
#include <cuda_runtime.h>
#include <math.h>
#include <stdint.h>

#define H        128
#define NC       10
#define NATT     3
#define B_TOTAL  16384
#define M_ROWS   128
#define THREADS  512
#define SSTR     132           // smem row stride (floats)
#define KT       10
#define KT2      (KT / 2)
#define EPS_LN   1e-5f

typedef unsigned long long ull;

// ---------------- smem layout (float offsets) ----------------
#define F_SW   0
#define F_SH   (F_SW + H * H)                 // 16384
#define F_SU   (F_SH + M_ROWS * SSTR)         // 33280
#define F_SB   (F_SU + M_ROWS * SSTR)         // 50176
#define F_SG   (F_SB + H)
#define F_SBE  (F_SG + H)
#define F_SWC  (F_SBE + H)
#define F_SBC  (F_SWC + H * NC)
#define F_TOT  (F_SBC + 16)

// ---------------- packed f32x2 helpers ----------------
__device__ __forceinline__ ull pack2(float lo, float hi) {
    ull r; asm("mov.b64 %0, {%1, %2};" : "=l"(r) : "f"(lo), "f"(hi)); return r;
}
__device__ __forceinline__ void unpack2(ull v, float& lo, float& hi) {
    asm("mov.b64 {%0, %1}, %2;" : "=f"(lo), "=f"(hi) : "l"(v));
}
__device__ __forceinline__ ull fma2(ull a, ull b, ull c) {
    ull d; asm("fma.rn.f32x2 %0, %1, %2, %3;" : "=l"(d) : "l"(a), "l"(b), "l"(c)); return d;
}
__device__ __forceinline__ ull add2(ull a, ull b) {
    ull d; asm("add.rn.f32x2 %0, %1, %2;" : "=l"(d) : "l"(a), "l"(b)); return d;
}
__device__ __forceinline__ ull mul2(ull a, ull b) {
    ull d; asm("mul.rn.f32x2 %0, %1, %2;" : "=l"(d) : "l"(a), "l"(b)); return d;
}

__device__ __forceinline__ float fast_tanh(float x)
{
    return 1.0f - 2.0f * __fdividef(1.0f, __expf(2.0f * x) + 1.0f);
}

// ---------------------------------------------------------------------------
// Register-tiled block GEMM (f32x2): Out[r][c] = In[r][:] @ Wm[:][c] + bias[c]
// Thread (rg, cg): rows r0..r0+3, cols {4cg..4cg+3} and {64+4cg..64+4cg+3}.
// ---------------------------------------------------------------------------
__device__ __forceinline__ void block_gemm(const float* __restrict__ In,
                                           const float* __restrict__ Wm,
                                           const float* __restrict__ bias,
                                           float* __restrict__ Out,
                                           int r0, int cA, int cB, bool do_tanh)
{
    ull acc[4][4];
#pragma unroll
    for (int i = 0; i < 4; i++)
#pragma unroll
        for (int j = 0; j < 4; j++) acc[i][j] = 0ull;

#pragma unroll 8
    for (int k4 = 0; k4 < H; k4 += 4) {
        float4 a0 = *(const float4*)&In[(r0 + 0) * SSTR + k4];
        float4 a1 = *(const float4*)&In[(r0 + 1) * SSTR + k4];
        float4 a2 = *(const float4*)&In[(r0 + 2) * SSTR + k4];
        float4 a3 = *(const float4*)&In[(r0 + 3) * SSTR + k4];
        float av0[4] = {a0.x, a0.y, a0.z, a0.w};
        float av1[4] = {a1.x, a1.y, a1.z, a1.w};
        float av2[4] = {a2.x, a2.y, a2.z, a2.w};
        float av3[4] = {a3.x, a3.y, a3.z, a3.w};
#pragma unroll
        for (int kk = 0; kk < 4; kk++) {
            ulonglong2 wa = *(const ulonglong2*)&Wm[(k4 + kk) * H + cA];
            ulonglong2 wb = *(const ulonglong2*)&Wm[(k4 + kk) * H + cB];
            ull p0 = pack2(av0[kk], av0[kk]);
            ull p1 = pack2(av1[kk], av1[kk]);
            ull p2 = pack2(av2[kk], av2[kk]);
            ull p3 = pack2(av3[kk], av3[kk]);
            acc[0][0] = fma2(p0, wa.x, acc[0][0]);
            acc[0][1] = fma2(p0, wa.y, acc[0][1]);
            acc[0][2] = fma2(p0, wb.x, acc[0][2]);
            acc[0][3] = fma2(p0, wb.y, acc[0][3]);
            acc[1][0] = fma2(p1, wa.x, acc[1][0]);
            acc[1][1] = fma2(p1, wa.y, acc[1][1]);
            acc[1][2] = fma2(p1, wb.x, acc[1][2]);
            acc[1][3] = fma2(p1, wb.y, acc[1][3]);
            acc[2][0] = fma2(p2, wa.x, acc[2][0]);
            acc[2][1] = fma2(p2, wa.y, acc[2][1]);
            acc[2][2] = fma2(p2, wb.x, acc[2][2]);
            acc[2][3] = fma2(p2, wb.y, acc[2][3]);
            acc[3][0] = fma2(p3, wa.x, acc[3][0]);
            acc[3][1] = fma2(p3, wa.y, acc[3][1]);
            acc[3][2] = fma2(p3, wb.x, acc[3][2]);
            acc[3][3] = fma2(p3, wb.y, acc[3][3]);
        }
    }

    ulonglong2 ba = *(const ulonglong2*)&bias[cA];
    ulonglong2 bb = *(const ulonglong2*)&bias[cB];
#pragma unroll
    for (int i = 0; i < 4; i++) {
        ull s0 = add2(acc[i][0], ba.x);
        ull s1 = add2(acc[i][1], ba.y);
        ull s2 = add2(acc[i][2], bb.x);
        ull s3 = add2(acc[i][3], bb.y);
        float v[8];
        unpack2(s0, v[0], v[1]);
        unpack2(s1, v[2], v[3]);
        unpack2(s2, v[4], v[5]);
        unpack2(s3, v[6], v[7]);
        if (do_tanh) {
#pragma unroll
            for (int j = 0; j < 8; j++) v[j] = fast_tanh(v[j]);
        }
        *(float4*)&Out[(r0 + i) * SSTR + cA] = make_float4(v[0], v[1], v[2], v[3]);
        *(float4*)&Out[(r0 + i) * SSTR + cB] = make_float4(v[4], v[5], v[6], v[7]);
    }
}

__global__ void __launch_bounds__(THREADS, 1)
simple_attention_kernel(const float* __restrict__ x,
                        const float* __restrict__ W_in,
                        const float* __restrict__ b_in,
                        const float* __restrict__ W_att,
                        const float* __restrict__ b_att,
                        const float* __restrict__ gamma,
                        const float* __restrict__ beta,
                        const float* __restrict__ W_c,
                        const float* __restrict__ b_c,
                        float* __restrict__ out)
{
    extern __shared__ float smem[];
    float* sW  = smem + F_SW;
    float* sH  = smem + F_SH;
    float* sU  = smem + F_SU;
    float* sB  = smem + F_SB;
    float* sG  = smem + F_SG;
    float* sBe = smem + F_SBE;
    float* sWc = smem + F_SWC;
    float* sBc = smem + F_SBC;

    const int tid  = threadIdx.x;
    const int base = blockIdx.x * M_ROWS;

    // GEMM mapping
    const int cg = tid & 15;
    const int rg = tid >> 4;
    const int r0 = rg * 4;
    const int cA = cg * 4;
    const int cB = 64 + cg * 4;

    // Epilogue row mapping: 4 lanes per row; lane pp owns j%4==pp
    const int rr = tid >> 2;
    const int pp = tid & 3;

    const float invf[KT] = {
        1.0f, 1.0f, 0.5f, 1.6666666667e-1f, 4.1666666667e-2f,
        8.3333333333e-3f, 1.3888888889e-3f, 1.9841269841e-4f,
        2.4801587302e-5f, 2.7557319224e-6f};

    float4* sW4 = (float4*)sW;

    // ---- stage x -> sU, W_in -> sW, W_c -> sWc (synchronous) ----
    {
        const float4* xg = (const float4*)(x + (size_t)base * H);
#pragma unroll
        for (int it = 0; it < 8; it++) {
            int i   = tid + it * THREADS;
            int row = i >> 5, c4 = i & 31;
            *(float4*)&sU[row * SSTR + c4 * 4] = xg[i];
        }
        const float4* wg = (const float4*)W_in;
#pragma unroll
        for (int it = 0; it < 8; it++)
            sW4[tid + it * THREADS] = wg[tid + it * THREADS];
        if (tid < (H * NC) / 4)
            ((float4*)sWc)[tid] = ((const float4*)W_c)[tid];
        if (tid < H)  sB[tid]  = b_in[tid];
        if (tid < NC) sBc[tid] = b_c[tid];
    }
    __syncthreads();

    // ---- in-proj: sH = x @ W_in + b_in ----
    block_gemm(sU, sW, sB, sH, r0, cA, cB, false);
    __syncthreads();

    // ---- stage W_att[0] + layer-0 vectors ----
    {
        const float4* wg = (const float4*)W_att;
#pragma unroll
        for (int it = 0; it < 8; it++)
            sW4[tid + it * THREADS] = wg[tid + it * THREADS];
        if (tid < H) {
            sB[tid]  = b_att[tid];
            sG[tid]  = gamma[tid];
            sBe[tid] = beta[tid];
        }
    }
    __syncthreads();

    // ---- attention layers ----
    for (int l = 0; l < NATT; l++) {
        const bool lastl = (l == NATT - 1);

        // u = tanh(h @ W + b) -> sU
        block_gemm(sH, sW, sB, sU, r0, cA, cB, true);
        __syncthreads();
        // sW is dead from here until the next GEMM: stage next-layer W during the
        // epilogue; with 16 warps/SM, staging stalls in one warp overlap with
        // epilogue math in the others.
        const float4* wgn = (const float4*)(W_att + (size_t)(l + 1) * H * H);

        if (!lastl) {
#pragma unroll
            for (int it = 0; it < 4; it++) {
                float4 t = wgn[tid + it * THREADS];
                sW4[tid + it * THREADS] = t;
            }
        }

        // ---- pass A: moments; keep u in registers ----
        float uarr[32];
        ull sm2[KT2], mm2[KT2];
#pragma unroll
        for (int p = 0; p < KT2; p++) { sm2[p] = 0ull; mm2[p] = 0ull; }

#pragma unroll
        for (int jj = 0; jj < 32; jj++) {
            int   j  = 4 * jj + pp;
            float u  = sU[rr * SSTR + j];
            float hv = sH[rr * SSTR + j];
            uarr[jj] = u;
            float uu = u * u;
            ull pwp = pack2(1.0f, u);
            ull u2d = pack2(uu, uu);
            ull hv2 = pack2(hv, hv);
#pragma unroll
            for (int p = 0; p < KT2; p++) {
                sm2[p] = add2(sm2[p], pwp);
                mm2[p] = fma2(pwp, hv2, mm2[p]);
                if (p < KT2 - 1) pwp = mul2(pwp, u2d);
            }
        }

        // stage second half of next W + next-layer vectors into regs
        float nb = 0.f, ng = 0.f, nbe = 0.f;
        if (!lastl) {
#pragma unroll
            for (int it = 4; it < 8; it++) {
                float4 t = wgn[tid + it * THREADS];
                sW4[tid + it * THREADS] = t;
            }
            if (tid < H) {
                nb  = b_att[(l + 1) * H + tid];
                ng  = gamma[(l + 1) * H + tid];
                nbe = beta[(l + 1) * H + tid];
            }
        }

        float sm[KT], mm[KT];
#pragma unroll
        for (int p = 0; p < KT2; p++) {
            unpack2(sm2[p], sm[2 * p], sm[2 * p + 1]);
            unpack2(mm2[p], mm[2 * p], mm[2 * p + 1]);
        }
#pragma unroll
        for (int k = 0; k < KT; k++) {
            sm[k] += __shfl_xor_sync(0xffffffffu, sm[k], 1);
            sm[k] += __shfl_xor_sync(0xffffffffu, sm[k], 2);
            mm[k] += __shfl_xor_sync(0xffffffffu, mm[k], 1);
            mm[k] += __shfl_xor_sync(0xffffffffu, mm[k], 2);
            sm[k] *= invf[k];
            mm[k] *= invf[k];
        }
        ull pm[KT];
#pragma unroll
        for (int k = 0; k < KT; k++) pm[k] = pack2(mm[k], sm[k]);

        // ---- pass B: Horner; z overwrites uarr; LN partials ----
        float lsum = 0.f, lsq = 0.f;
#pragma unroll
        for (int jj = 0; jj < 32; jj++) {
            int   j  = 4 * jj + pp;
            float u  = uarr[jj];
            float hv = sH[rr * SSTR + j];
            ull   u2 = pack2(u, u);
            ull   nd = pm[KT - 1];
#pragma unroll
            for (int k = KT - 2; k >= 0; k--)
                nd = fma2(nd, u2, pm[k]);
            float num, den;
            unpack2(nd, num, den);
            float z = hv + __fdividef(num, den);
            uarr[jj] = z;
            lsum += z;
            lsq  = fmaf(z, z, lsq);
        }
        lsum += __shfl_xor_sync(0xffffffffu, lsum, 1);
        lsum += __shfl_xor_sync(0xffffffffu, lsum, 2);
        lsq  += __shfl_xor_sync(0xffffffffu, lsq, 1);
        lsq  += __shfl_xor_sync(0xffffffffu, lsq, 2);

        float mu   = lsum * (1.f / H);
        float var  = lsq * (1.f / H) - mu * mu;
        float rinv = rsqrtf(var + EPS_LN);

        // ---- pass C: LN apply -> sH (or fused classifier on last layer) ----
        if (!lastl) {
#pragma unroll
            for (int jj = 0; jj < 32; jj++) {
                int   j = 4 * jj + pp;
                float z = uarr[jj];
                sH[rr * SSTR + j] = fmaf((z - mu) * rinv, sG[j], sBe[j]);
            }
            __syncthreads();                 // all pass-C sG/sBe reads complete
            if (tid < H) { sB[tid] = nb; sG[tid] = ng; sBe[tid] = nbe; }
            __syncthreads();                 // new W (already stored) + vectors visible
        } else {
            ull acc2[NC / 2];
#pragma unroll
            for (int c = 0; c < NC / 2; c++) acc2[c] = 0ull;
#pragma unroll
            for (int jj = 0; jj < 32; jj++) {
                int   j  = 4 * jj + pp;
                float z  = uarr[jj];
                float hn = fmaf((z - mu) * rinv, sG[j], sBe[j]);
                ull hn2 = pack2(hn, hn);
#pragma unroll
                for (int c = 0; c < NC / 2; c++) {
                    ull wp = *(const ull*)&sWc[j * NC + 2 * c];
                    acc2[c] = fma2(hn2, wp, acc2[c]);
                }
            }
            float acc[NC];
#pragma unroll
            for (int c = 0; c < NC / 2; c++) unpack2(acc2[c], acc[2 * c], acc[2 * c + 1]);
#pragma unroll
            for (int c = 0; c < NC; c++) {
                acc[c] += __shfl_xor_sync(0xffffffffu, acc[c], 1);
                acc[c] += __shfl_xor_sync(0xffffffffu, acc[c], 2);
            }
            if (pp == 0) {
#pragma unroll
                for (int c = 0; c < NC; c++)
                    out[(size_t)(base + rr) * NC + c] = acc[c] + sBc[c];
            }
        }
    }
}

extern "C" void kernel_launch(void* const* d_in, const int* in_sizes, int n_in,
                              void* d_out, int out_size)
{
    const float* x     = (const float*)d_in[0];
    const float* W_in  = (const float*)d_in[1];
    const float* b_in  = (const float*)d_in[2];
    const float* W_att = (const float*)d_in[3];
    const float* b_att = (const float*)d_in[4];
    const float* gam   = (const float*)d_in[5];
    const float* bet   = (const float*)d_in[6];
    const float* W_c   = (const float*)d_in[7];
    const float* b_c   = (const float*)d_in[8];

    size_t smem_bytes = (size_t)F_TOT * sizeof(float);
    cudaFuncSetAttribute(simple_attention_kernel,
                         cudaFuncAttributeMaxDynamicSharedMemorySize,
                         (int)smem_bytes);

    simple_attention_kernel<<<B_TOTAL / M_ROWS, THREADS, smem_bytes>>>(
        x, W_in, b_in, W_att, b_att, gam, bet, W_c, b_c, (float*)d_out);
}

// round 10
// speedup vs baseline: 2.1087x; 1.4253x over previous
#include <cuda_runtime.h>
#include <cuda_bf16.h>
#include <math.h>
#include <stdint.h>

#define H        128
#define NC       10
#define NATT     3
#define B_TOTAL  16384
#define M_ROWS   128
#define THREADS  512
#define KT       8
#define KT2      4
#define EPS_LN   1e-5f
#define SBB      272          // bytes per bf16 tile row (136 bf16; 17x16B -> ldmatrix conflict-free)

typedef unsigned long long ull;

// ---------------- smem byte layout ----------------
#define O_AHI  0
#define O_ALO  (O_AHI + 128 * SBB)            // 34816
#define O_WHI  (O_ALO + 128 * SBB)
#define O_WLO  (O_WHI + 128 * SBB)
#define O_PART (O_WLO + 128 * SBB)            // 139264
#define PART_STRIDE 68                         // floats per row
#define O_FIN  (O_PART + 128 * PART_STRIDE * 4)
#define FIN_STRIDE 20
#define O_LN   (O_FIN + 128 * FIN_STRIDE * 4)
#define LN_STRIDE 12
#define O_VEC  (O_LN + 128 * LN_STRIDE * 4)
// vector area (float offsets from O_VEC): bias[4][128] (in-proj + 3 att), g[3][128], be[3][128], Wc, bc
#define VF_BIAS 0
#define VF_G    (VF_BIAS + 4 * 128)
#define VF_BE   (VF_G + 3 * 128)
#define VF_WC   (VF_BE + 3 * 128)
#define VF_BC   (VF_WC + H * NC)
#define VF_TOT  (VF_BC + 16)
#define SMEM_TOTAL (O_VEC + VF_TOT * 4)        // 200768 B

// ---------------- f32x2 helpers ----------------
__device__ __forceinline__ ull pack2(float lo, float hi) {
    ull r; asm("mov.b64 %0, {%1, %2};" : "=l"(r) : "f"(lo), "f"(hi)); return r;
}
__device__ __forceinline__ void unpack2(ull v, float& lo, float& hi) {
    asm("mov.b64 {%0, %1}, %2;" : "=f"(lo), "=f"(hi) : "l"(v));
}
__device__ __forceinline__ ull fma2(ull a, ull b, ull c) {
    ull d; asm("fma.rn.f32x2 %0, %1, %2, %3;" : "=l"(d) : "l"(a), "l"(b), "l"(c)); return d;
}
__device__ __forceinline__ ull add2(ull a, ull b) {
    ull d; asm("add.rn.f32x2 %0, %1, %2;" : "=l"(d) : "l"(a), "l"(b)); return d;
}
__device__ __forceinline__ ull mul2(ull a, ull b) {
    ull d; asm("mul.rn.f32x2 %0, %1, %2;" : "=l"(d) : "l"(a), "l"(b)); return d;
}

__device__ __forceinline__ uint32_t smem_u32(const void* p) {
    uint32_t a;
    asm("{ .reg .u64 t; cvta.to.shared.u64 t, %1; cvt.u32.u64 %0, t; }" : "=r"(a) : "l"(p));
    return a;
}

// ---------------- tensor-core primitives (base PTX, sm_80+) ----------------
#define LDSM4(r, addr)                                                          \
    asm volatile("ldmatrix.sync.aligned.m8n8.x4.shared.b16 {%0,%1,%2,%3}, [%4];" \
        : "=r"((r)[0]), "=r"((r)[1]), "=r"((r)[2]), "=r"((r)[3]) : "r"(addr))

#define MMA_BF16(d, a, b0, b1)                                                  \
    asm volatile("mma.sync.aligned.m16n8k16.row.col.f32.bf16.bf16.f32 "         \
        "{%0,%1,%2,%3}, {%4,%5,%6,%7}, {%8,%9}, {%0,%1,%2,%3};"                 \
        : "+f"((d)[0]), "+f"((d)[1]), "+f"((d)[2]), "+f"((d)[3])                \
        : "r"((a)[0]), "r"((a)[1]), "r"((a)[2]), "r"((a)[3]), "r"(b0), "r"(b1))

// ---------------- bf16 split/join ----------------
union BU { __nv_bfloat162 b; uint32_t u; };
__device__ __forceinline__ void split2(float v0, float v1, uint32_t& hi2, uint32_t& lo2) {
    BU h; h.b = __floats2bfloat162_rn(v0, v1);
    float r0 = v0 - __bfloat162float(__low2bfloat16(h.b));
    float r1 = v1 - __bfloat162float(__high2bfloat16(h.b));
    BU l; l.b = __floats2bfloat162_rn(r0, r1);
    hi2 = h.u; lo2 = l.u;
}
__device__ __forceinline__ float2 join2(uint32_t hi2, uint32_t lo2) {
    BU a, b; a.u = hi2; b.u = lo2;
    float2 r;
    r.x = __bfloat162float(__low2bfloat16(a.b))  + __bfloat162float(__low2bfloat16(b.b));
    r.y = __bfloat162float(__high2bfloat16(a.b)) + __bfloat162float(__high2bfloat16(b.b));
    return r;
}

__device__ __forceinline__ float fast_tanh(float x) {
    return 1.0f - 2.0f * __fdividef(1.0f, __expf(2.0f * x) + 1.0f);
}

// Taylor moment accumulate (pair-stride: {u^0,u^1} advanced by {u^2,u^2})
__device__ __forceinline__ void mom_acc(ull sm2[KT2], ull mm2[KT2], float u, float h) {
    float uu = u * u;
    ull pwp = pack2(1.0f, u);
    ull u2d = pack2(uu, uu);
    ull h2  = pack2(h, h);
#pragma unroll
    for (int p = 0; p < KT2; p++) {
        sm2[p] = add2(sm2[p], pwp);
        mm2[p] = fma2(pwp, h2, mm2[p]);
        if (p < KT2 - 1) pwp = mul2(pwp, u2d);
    }
}

// 3-pass bf16-split GEMM: D[128x128] = A[128x128] @ Wt[128x128]^T, fp32 accum in regs
__device__ __forceinline__ void mma_gemm(uint32_t sb, uint32_t aOff, uint32_t bOff,
                                         float d[2][4][4]) {
#pragma unroll
    for (int mi = 0; mi < 2; mi++)
#pragma unroll
        for (int na = 0; na < 4; na++)
#pragma unroll
            for (int e = 0; e < 4; e++) d[mi][na][e] = 0.f;

    const uint32_t aHi = sb + O_AHI + aOff, aLo = sb + O_ALO + aOff;
    const uint32_t bHi = sb + O_WHI + bOff, bLo = sb + O_WLO + bOff;
#pragma unroll
    for (int kk = 0; kk < 8; kk++) {
        uint32_t ko = kk * 32;                     // 16 bf16 = 32 B per k-step
        uint32_t ahi0[4], ahi1[4], alo0[4], alo1[4];
        uint32_t bhi0[4], bhi1[4], blo0[4], blo1[4];
        LDSM4(ahi0, aHi + ko);
        LDSM4(ahi1, aHi + 16 * SBB + ko);
        LDSM4(alo0, aLo + ko);
        LDSM4(alo1, aLo + 16 * SBB + ko);
        LDSM4(bhi0, bHi + ko);
        LDSM4(bhi1, bHi + 16 * SBB + ko);
        LDSM4(blo0, bLo + ko);
        LDSM4(blo1, bLo + 16 * SBB + ko);
#pragma unroll
        for (int mi = 0; mi < 2; mi++) {
            uint32_t* ah = mi ? ahi1 : ahi0;
            uint32_t* al = mi ? alo1 : alo0;
#pragma unroll
            for (int np = 0; np < 2; np++) {
                uint32_t* bh = np ? bhi1 : bhi0;
                uint32_t* bl = np ? blo1 : blo0;
#pragma unroll
                for (int ns = 0; ns < 2; ns++) {
                    float* dd = d[mi][np * 2 + ns];
                    MMA_BF16(dd, ah, bh[2 * ns], bh[2 * ns + 1]);
                    MMA_BF16(dd, ah, bl[2 * ns], bl[2 * ns + 1]);
                    MMA_BF16(dd, al, bh[2 * ns], bh[2 * ns + 1]);
                }
            }
        }
    }
}

// stage W[k][n] (row-major) -> Wt tiles [n][k] bf16 hi/lo
__device__ __forceinline__ void stage_w(char* smem, const float* __restrict__ Wg, int tid) {
#pragma unroll
    for (int it = 0; it < 16; it++) {
        int idx = tid + it * THREADS;              // 8192 k-pairs
        int n = idx & 127, k2 = idx >> 7;
        float w0 = Wg[(2 * k2) * H + n];
        float w1 = Wg[(2 * k2 + 1) * H + n];
        uint32_t hi2, lo2; split2(w0, w1, hi2, lo2);
        uint32_t off = (uint32_t)n * SBB + (uint32_t)k2 * 4;
        *(uint32_t*)(smem + O_WHI + off) = hi2;
        *(uint32_t*)(smem + O_WLO + off) = lo2;
    }
}

__global__ void __launch_bounds__(THREADS, 1)
simple_attention_kernel(const float* __restrict__ x,
                        const float* __restrict__ W_in,
                        const float* __restrict__ b_in,
                        const float* __restrict__ W_att,
                        const float* __restrict__ b_att,
                        const float* __restrict__ gamma,
                        const float* __restrict__ beta,
                        const float* __restrict__ W_c,
                        const float* __restrict__ b_c,
                        float* __restrict__ out)
{
    extern __shared__ char smem[];
    const uint32_t sb = smem_u32(smem);
    float* part = (float*)(smem + O_PART);
    float* fin  = (float*)(smem + O_FIN);
    float* lns  = (float*)(smem + O_LN);
    float* vec  = (float*)(smem + O_VEC);

    const int tid  = threadIdx.x;
    const int wid  = tid >> 5, lane = tid & 31;
    const int base = blockIdx.x * M_ROWS;
    const int m0 = (wid & 3) * 32;
    const int n0 = (wid >> 2) * 32;
    const int wc = wid >> 2;

    // ldmatrix per-thread byte offsets within a tile
    const uint32_t aOff = (uint32_t)(m0 + (lane & 15)) * SBB + ((uint32_t)(lane >> 4) << 4);
    const uint32_t bOff = (uint32_t)(n0 + ((lane >> 4) << 3) + (lane & 7)) * SBB
                        + ((uint32_t)((lane >> 3) & 1) << 4);

    // epilogue element mapping: rows rBase + mi*16 + ri*8; cols cBase + na*8 (+0/1)
    const int rBase = m0 + (lane >> 2);
    const int cBase = n0 + (lane & 3) * 2;

    const float invf[KT] = {1.0f, 1.0f, 0.5f, 1.6666666667e-1f, 4.1666666667e-2f,
                            8.3333333333e-3f, 1.3888888889e-3f, 1.9841269841e-4f};

    // ---------------- initial staging ----------------
#pragma unroll
    for (int it = 0; it < 16; it++) {
        int idx = tid + it * THREADS;              // 8192 col-pairs of x
        int row = idx >> 6, kp = idx & 63;
        float2 v = *(const float2*)(x + (size_t)(base + row) * H + 2 * kp);
        uint32_t hi2, lo2; split2(v.x, v.y, hi2, lo2);
        uint32_t off = (uint32_t)row * SBB + (uint32_t)kp * 4;
        *(uint32_t*)(smem + O_AHI + off) = hi2;
        *(uint32_t*)(smem + O_ALO + off) = lo2;
    }
    stage_w(smem, W_in, tid);
    if (tid < 128) vec[VF_BIAS + tid] = b_in[tid];
    for (int i = tid; i < 3 * 128; i += THREADS) {
        vec[VF_BIAS + 128 + i] = b_att[i];
        vec[VF_G + i]  = gamma[i];
        vec[VF_BE + i] = beta[i];
    }
    for (int i = tid; i < H * NC; i += THREADS) vec[VF_WC + i] = W_c[i];
    if (tid < NC) vec[VF_BC + tid] = b_c[tid];
    __syncthreads();

    float d[2][4][4];

    // ---------------- in-proj GEMM + epilogue ----------------
    mma_gemm(sb, aOff, bOff, d);
    __syncthreads();
    stage_w(smem, W_att, tid);                     // layer-0 W into dead Wt
    {
        const float* sBias = vec + VF_BIAS;
#pragma unroll
        for (int mi = 0; mi < 2; mi++)
#pragma unroll
        for (int ri = 0; ri < 2; ri++) {
            int row = rBase + mi * 16 + ri * 8;
#pragma unroll
            for (int na = 0; na < 4; na++) {
                int col = cBase + na * 8;
                float v0 = d[mi][na][2 * ri]     + sBias[col];
                float v1 = d[mi][na][2 * ri + 1] + sBias[col + 1];
                uint32_t hi2, lo2; split2(v0, v1, hi2, lo2);
                uint32_t off = (uint32_t)row * SBB + (uint32_t)col * 2;
                *(uint32_t*)(smem + O_AHI + off) = hi2;
                *(uint32_t*)(smem + O_ALO + off) = lo2;
            }
        }
    }
    __syncthreads();

    // ---------------- attention layers ----------------
    for (int l = 0; l < NATT; l++) {
        const bool lastl = (l == NATT - 1);
        mma_gemm(sb, aOff, bOff, d);
        __syncthreads();
        if (!lastl) stage_w(smem, W_att + (size_t)(l + 1) * H * H, tid);

        const float* sBias = vec + VF_BIAS + 128 + l * 128;
        const float* sG    = vec + VF_G + l * 128;
        const float* sBe   = vec + VF_BE + l * 128;

        // ---- pass A: u = tanh(D+b) in regs; Taylor moments; quad-shfl; part ----
#pragma unroll
        for (int mi = 0; mi < 2; mi++)
#pragma unroll
        for (int ri = 0; ri < 2; ri++) {
            int row = rBase + mi * 16 + ri * 8;
            ull sm2[KT2], mm2[KT2];
#pragma unroll
            for (int p = 0; p < KT2; p++) { sm2[p] = 0ull; mm2[p] = 0ull; }
#pragma unroll
            for (int na = 0; na < 4; na++) {
                int col = cBase + na * 8;
                float u0 = fast_tanh(d[mi][na][2 * ri]     + sBias[col]);
                float u1 = fast_tanh(d[mi][na][2 * ri + 1] + sBias[col + 1]);
                d[mi][na][2 * ri]     = u0;
                d[mi][na][2 * ri + 1] = u1;
                uint32_t off = (uint32_t)row * SBB + (uint32_t)col * 2;
                float2 h = join2(*(const uint32_t*)(smem + O_AHI + off),
                                 *(const uint32_t*)(smem + O_ALO + off));
                mom_acc(sm2, mm2, u0, h.x);
                mom_acc(sm2, mm2, u1, h.y);
            }
            float v16[16];
#pragma unroll
            for (int p = 0; p < KT2; p++) {
                unpack2(sm2[p], v16[2 * p], v16[2 * p + 1]);
                unpack2(mm2[p], v16[8 + 2 * p], v16[8 + 2 * p + 1]);
            }
#pragma unroll
            for (int k = 0; k < 16; k++) {
                v16[k] += __shfl_xor_sync(0xffffffffu, v16[k], 1);
                v16[k] += __shfl_xor_sync(0xffffffffu, v16[k], 2);
            }
            int j = lane & 3;
            *(float4*)&part[row * PART_STRIDE + wc * 16 + j * 4] =
                make_float4(v16[j * 4], v16[j * 4 + 1], v16[j * 4 + 2], v16[j * 4 + 3]);
        }
        __syncthreads();

        // ---- stage 2: sum partials over the 4 col-warps ----
        {
            int row = tid >> 2, j = tid & 3;
            float4 s = *(const float4*)&part[row * PART_STRIDE + 0 * 16 + j * 4];
#pragma unroll
            for (int q = 1; q < 4; q++) {
                float4 t = *(const float4*)&part[row * PART_STRIDE + q * 16 + j * 4];
                s.x += t.x; s.y += t.y; s.z += t.z; s.w += t.w;
            }
            *(float4*)&fin[row * FIN_STRIDE + j * 4] = s;
        }
        __syncthreads();

        // ---- pass B: Horner out, z in regs, LN partials ----
#pragma unroll
        for (int mi = 0; mi < 2; mi++)
#pragma unroll
        for (int ri = 0; ri < 2; ri++) {
            int row = rBase + mi * 16 + ri * 8;
            float4 f0 = *(const float4*)&fin[row * FIN_STRIDE + 0];
            float4 f1 = *(const float4*)&fin[row * FIN_STRIDE + 4];
            float4 f2 = *(const float4*)&fin[row * FIN_STRIDE + 8];
            float4 f3 = *(const float4*)&fin[row * FIN_STRIDE + 12];
            float smv[8] = {f0.x, f0.y, f0.z, f0.w, f1.x, f1.y, f1.z, f1.w};
            float mmv[8] = {f2.x, f2.y, f2.z, f2.w, f3.x, f3.y, f3.z, f3.w};
            ull pm[KT];
#pragma unroll
            for (int k = 0; k < KT; k++) pm[k] = pack2(mmv[k] * invf[k], smv[k] * invf[k]);

            float lsum = 0.f, lsq = 0.f;
#pragma unroll
            for (int na = 0; na < 4; na++) {
                int col = cBase + na * 8;
                uint32_t off = (uint32_t)row * SBB + (uint32_t)col * 2;
                float2 h = join2(*(const uint32_t*)(smem + O_AHI + off),
                                 *(const uint32_t*)(smem + O_ALO + off));
#pragma unroll
                for (int ci = 0; ci < 2; ci++) {
                    float u = d[mi][na][2 * ri + ci];
                    ull u2 = pack2(u, u);
                    ull nd = pm[KT - 1];
#pragma unroll
                    for (int k = KT - 2; k >= 0; k--) nd = fma2(nd, u2, pm[k]);
                    float num, den; unpack2(nd, num, den);
                    float z = (ci ? h.y : h.x) + __fdividef(num, den);
                    d[mi][na][2 * ri + ci] = z;
                    lsum += z;
                    lsq = fmaf(z, z, lsq);
                }
            }
            lsum += __shfl_xor_sync(0xffffffffu, lsum, 1);
            lsum += __shfl_xor_sync(0xffffffffu, lsum, 2);
            lsq  += __shfl_xor_sync(0xffffffffu, lsq, 1);
            lsq  += __shfl_xor_sync(0xffffffffu, lsq, 2);
            if ((lane & 3) == 0)
                *(float2*)&lns[row * LN_STRIDE + wc * 2] = make_float2(lsum, lsq);
        }
        __syncthreads();

        // ---- pass C: LN apply -> A tiles, or fused classifier ----
        if (!lastl) {
#pragma unroll
            for (int mi = 0; mi < 2; mi++)
#pragma unroll
            for (int ri = 0; ri < 2; ri++) {
                int row = rBase + mi * 16 + ri * 8;
                float tsum = 0.f, tsq = 0.f;
#pragma unroll
                for (int q = 0; q < 4; q++) {
                    float2 t = *(const float2*)&lns[row * LN_STRIDE + q * 2];
                    tsum += t.x; tsq += t.y;
                }
                float mu   = tsum * (1.f / H);
                float var  = tsq * (1.f / H) - mu * mu;
                float rinv = rsqrtf(var + EPS_LN);
#pragma unroll
                for (int na = 0; na < 4; na++) {
                    int col = cBase + na * 8;
                    float hn0 = fmaf((d[mi][na][2 * ri]     - mu) * rinv, sG[col],     sBe[col]);
                    float hn1 = fmaf((d[mi][na][2 * ri + 1] - mu) * rinv, sG[col + 1], sBe[col + 1]);
                    uint32_t hi2, lo2; split2(hn0, hn1, hi2, lo2);
                    uint32_t off = (uint32_t)row * SBB + (uint32_t)col * 2;
                    *(uint32_t*)(smem + O_AHI + off) = hi2;
                    *(uint32_t*)(smem + O_ALO + off) = lo2;
                }
            }
            __syncthreads();
        } else {
            const float* sWc = vec + VF_WC;
#pragma unroll
            for (int mi = 0; mi < 2; mi++)
#pragma unroll
            for (int ri = 0; ri < 2; ri++) {
                int row = rBase + mi * 16 + ri * 8;
                float tsum = 0.f, tsq = 0.f;
#pragma unroll
                for (int q = 0; q < 4; q++) {
                    float2 t = *(const float2*)&lns[row * LN_STRIDE + q * 2];
                    tsum += t.x; tsq += t.y;
                }
                float mu   = tsum * (1.f / H);
                float var  = tsq * (1.f / H) - mu * mu;
                float rinv = rsqrtf(var + EPS_LN);
                float acc[NC];
#pragma unroll
                for (int c = 0; c < NC; c++) acc[c] = 0.f;
#pragma unroll
                for (int na = 0; na < 4; na++) {
                    int col = cBase + na * 8;
                    float hn0 = fmaf((d[mi][na][2 * ri]     - mu) * rinv, sG[col],     sBe[col]);
                    float hn1 = fmaf((d[mi][na][2 * ri + 1] - mu) * rinv, sG[col + 1], sBe[col + 1]);
#pragma unroll
                    for (int c = 0; c < NC; c++)
                        acc[c] += hn0 * sWc[col * NC + c] + hn1 * sWc[(col + 1) * NC + c];
                }
#pragma unroll
                for (int c = 0; c < NC; c++) {
                    acc[c] += __shfl_xor_sync(0xffffffffu, acc[c], 1);
                    acc[c] += __shfl_xor_sync(0xffffffffu, acc[c], 2);
                }
                if ((lane & 3) == 0) {
                    float* p = &part[row * PART_STRIDE + wc * 10];
#pragma unroll
                    for (int c = 0; c < NC; c += 2)
                        *(float2*)&p[c] = make_float2(acc[c], acc[c + 1]);
                }
            }
            __syncthreads();
            if (tid < 128) {
                float o[NC];
#pragma unroll
                for (int c = 0; c < NC; c++) o[c] = vec[VF_BC + c];
#pragma unroll
                for (int q = 0; q < 4; q++)
#pragma unroll
                    for (int c = 0; c < NC; c++)
                        o[c] += part[tid * PART_STRIDE + q * 10 + c];
                float* og = out + (size_t)(base + tid) * NC;
#pragma unroll
                for (int c = 0; c < NC; c += 2)
                    *(float2*)&og[c] = make_float2(o[c], o[c + 1]);
            }
        }
    }
}

extern "C" void kernel_launch(void* const* d_in, const int* in_sizes, int n_in,
                              void* d_out, int out_size)
{
    const float* x     = (const float*)d_in[0];
    const float* W_in  = (const float*)d_in[1];
    const float* b_in  = (const float*)d_in[2];
    const float* W_att = (const float*)d_in[3];
    const float* b_att = (const float*)d_in[4];
    const float* gam   = (const float*)d_in[5];
    const float* bet   = (const float*)d_in[6];
    const float* W_c   = (const float*)d_in[7];
    const float* b_c   = (const float*)d_in[8];

    cudaFuncSetAttribute(simple_attention_kernel,
                         cudaFuncAttributeMaxDynamicSharedMemorySize, SMEM_TOTAL);

    simple_attention_kernel<<<B_TOTAL / M_ROWS, THREADS, SMEM_TOTAL>>>(
        x, W_in, b_in, W_att, b_att, gam, bet, W_c, b_c, (float*)d_out);
}

// round 11
// speedup vs baseline: 2.2379x; 1.0613x over previous
#include <cuda_runtime.h>
#include <cuda_bf16.h>
#include <math.h>
#include <stdint.h>

#define H        128
#define NC       10
#define NATT     3
#define B_TOTAL  16384
#define M_ROWS   128
#define THREADS  512
#define KT       8
#define KT2      4
#define EPS_LN   1e-5f
#define SBB      272          // A-tile row stride bytes (m-major)
#define SBW      272          // W-tile row stride bytes (k-major)

typedef unsigned long long ull;

// ---------------- smem byte layout ----------------
#define O_AHI  0
#define O_ALO  (O_AHI + 128 * SBB)
#define O_WHI  (O_ALO + 128 * SBB)
#define O_WLO  (O_WHI + 128 * SBW)
#define O_PART (O_WLO + 128 * SBW)
#define PART_STRIDE 68
#define O_FIN  (O_PART + 128 * PART_STRIDE * 4)
#define FIN_STRIDE 20
#define O_LN   (O_FIN + 128 * FIN_STRIDE * 4)
#define LN_STRIDE 12
#define O_VEC  (O_LN + 128 * LN_STRIDE * 4)
#define VF_BIAS 0
#define VF_G    (VF_BIAS + 4 * 128)
#define VF_BE   (VF_G + 3 * 128)
#define VF_WC   (VF_BE + 3 * 128)
#define VF_BC   (VF_WC + H * NC)
#define VF_TOT  (VF_BC + 16)
#define SMEM_TOTAL (O_VEC + VF_TOT * 4)

// ---------------- f32x2 helpers ----------------
__device__ __forceinline__ ull pack2(float lo, float hi) {
    ull r; asm("mov.b64 %0, {%1, %2};" : "=l"(r) : "f"(lo), "f"(hi)); return r;
}
__device__ __forceinline__ void unpack2(ull v, float& lo, float& hi) {
    asm("mov.b64 {%0, %1}, %2;" : "=f"(lo), "=f"(hi) : "l"(v));
}
__device__ __forceinline__ ull fma2(ull a, ull b, ull c) {
    ull d; asm("fma.rn.f32x2 %0, %1, %2, %3;" : "=l"(d) : "l"(a), "l"(b), "l"(c)); return d;
}
__device__ __forceinline__ ull add2(ull a, ull b) {
    ull d; asm("add.rn.f32x2 %0, %1, %2;" : "=l"(d) : "l"(a), "l"(b)); return d;
}
__device__ __forceinline__ ull mul2(ull a, ull b) {
    ull d; asm("mul.rn.f32x2 %0, %1, %2;" : "=l"(d) : "l"(a), "l"(b)); return d;
}

__device__ __forceinline__ uint32_t smem_u32(const void* p) {
    uint32_t a;
    asm("{ .reg .u64 t; cvta.to.shared.u64 t, %1; cvt.u32.u64 %0, t; }" : "=r"(a) : "l"(p));
    return a;
}

// ---------------- tensor-core primitives ----------------
#define LDSM4(r, addr)                                                          \
    asm volatile("ldmatrix.sync.aligned.m8n8.x4.shared.b16 {%0,%1,%2,%3}, [%4];" \
        : "=r"((r)[0]), "=r"((r)[1]), "=r"((r)[2]), "=r"((r)[3]) : "r"(addr))
#define LDSM4T(r, addr)                                                         \
    asm volatile("ldmatrix.sync.aligned.m8n8.x4.trans.shared.b16 {%0,%1,%2,%3}, [%4];" \
        : "=r"((r)[0]), "=r"((r)[1]), "=r"((r)[2]), "=r"((r)[3]) : "r"(addr))

#define MMA_BF16(d, a, b0, b1)                                                  \
    asm volatile("mma.sync.aligned.m16n8k16.row.col.f32.bf16.bf16.f32 "         \
        "{%0,%1,%2,%3}, {%4,%5,%6,%7}, {%8,%9}, {%0,%1,%2,%3};"                 \
        : "+f"((d)[0]), "+f"((d)[1]), "+f"((d)[2]), "+f"((d)[3])                \
        : "r"((a)[0]), "r"((a)[1]), "r"((a)[2]), "r"((a)[3]), "r"(b0), "r"(b1))

// group barrier: 4 warps (128 threads) sharing one m-row-group
#define BARG(g) asm volatile("bar.sync %0, %1;" :: "r"((g) + 1), "r"(128) : "memory")

// ---------------- bf16 split/join ----------------
union BU { __nv_bfloat162 b; uint32_t u; };
__device__ __forceinline__ void split2(float v0, float v1, uint32_t& hi2, uint32_t& lo2) {
    BU h; h.b = __floats2bfloat162_rn(v0, v1);
    float r0 = v0 - __bfloat162float(__low2bfloat16(h.b));
    float r1 = v1 - __bfloat162float(__high2bfloat16(h.b));
    BU l; l.b = __floats2bfloat162_rn(r0, r1);
    hi2 = h.u; lo2 = l.u;
}
__device__ __forceinline__ float2 join2(uint32_t hi2, uint32_t lo2) {
    BU a, b; a.u = hi2; b.u = lo2;
    float2 r;
    r.x = __bfloat162float(__low2bfloat16(a.b))  + __bfloat162float(__low2bfloat16(b.b));
    r.y = __bfloat162float(__high2bfloat16(a.b)) + __bfloat162float(__high2bfloat16(b.b));
    return r;
}

__device__ __forceinline__ float fast_tanh(float x) {
    return 1.0f - 2.0f * __fdividef(1.0f, __expf(2.0f * x) + 1.0f);
}

__device__ __forceinline__ void mom_acc(ull sm2[KT2], ull mm2[KT2], float u, float h) {
    float uu = u * u;
    ull pwp = pack2(1.0f, u);
    ull u2d = pack2(uu, uu);
    ull h2  = pack2(h, h);
#pragma unroll
    for (int p = 0; p < KT2; p++) {
        sm2[p] = add2(sm2[p], pwp);
        mm2[p] = fma2(pwp, h2, mm2[p]);
        if (p < KT2 - 1) pwp = mul2(pwp, u2d);
    }
}

// 3-pass bf16-split GEMM. A tile m-major (non-trans LDSM); W tile k-major (trans LDSM).
__device__ __forceinline__ void mma_gemm(uint32_t sb, uint32_t aOff, uint32_t bOffT,
                                         float d[2][4][4]) {
#pragma unroll
    for (int mi = 0; mi < 2; mi++)
#pragma unroll
        for (int na = 0; na < 4; na++)
#pragma unroll
            for (int e = 0; e < 4; e++) d[mi][na][e] = 0.f;

    const uint32_t aHi = sb + O_AHI + aOff, aLo = sb + O_ALO + aOff;
    const uint32_t bHi = sb + O_WHI + bOffT, bLo = sb + O_WLO + bOffT;
#pragma unroll
    for (int kk = 0; kk < 8; kk++) {
        uint32_t ko  = kk * 32;            // A: 16 bf16 = 32 B per k-step
        uint32_t bko = kk * 16 * SBW;      // W: 16 k-rows per k-step
        uint32_t ahi0[4], ahi1[4], alo0[4], alo1[4];
        uint32_t bhi0[4], bhi1[4], blo0[4], blo1[4];
        LDSM4(ahi0, aHi + ko);
        LDSM4(ahi1, aHi + 16 * SBB + ko);
        LDSM4(alo0, aLo + ko);
        LDSM4(alo1, aLo + 16 * SBB + ko);
        LDSM4T(bhi0, bHi + bko);
        LDSM4T(bhi1, bHi + bko + 32);      // second n16 chunk: +16 cols = +32 B
        LDSM4T(blo0, bLo + bko);
        LDSM4T(blo1, bLo + bko + 32);
#pragma unroll
        for (int mi = 0; mi < 2; mi++) {
            uint32_t* ah = mi ? ahi1 : ahi0;
            uint32_t* al = mi ? alo1 : alo0;
#pragma unroll
            for (int np = 0; np < 2; np++) {
                uint32_t* bh = np ? bhi1 : bhi0;
                uint32_t* bl = np ? blo1 : blo0;
#pragma unroll
                for (int ns = 0; ns < 2; ns++) {
                    float* dd = d[mi][np * 2 + ns];
                    MMA_BF16(dd, ah, bh[2 * ns], bh[2 * ns + 1]);
                    MMA_BF16(dd, ah, bl[2 * ns], bl[2 * ns + 1]);
                    MMA_BF16(dd, al, bh[2 * ns], bh[2 * ns + 1]);
                }
            }
        }
    }
}

// stage W[k][n] row-major -> k-major tile (straight copy, bf16 hi/lo).
// Global reads and smem writes both fully coalesced, conflict-free.
__device__ __forceinline__ void stage_w(char* smem, const float* __restrict__ Wg, int tid) {
#pragma unroll
    for (int it = 0; it < 16; it++) {
        int idx = tid + it * THREADS;          // 8192 = 128 k-rows x 64 n-pairs
        int k = idx >> 6, np = idx & 63;
        float2 w = *(const float2*)(Wg + (size_t)k * H + 2 * np);
        uint32_t hi2, lo2; split2(w.x, w.y, hi2, lo2);
        uint32_t off = (uint32_t)k * SBW + (uint32_t)np * 4;
        *(uint32_t*)(smem + O_WHI + off) = hi2;
        *(uint32_t*)(smem + O_WLO + off) = lo2;
    }
}

__global__ void __launch_bounds__(THREADS, 1)
simple_attention_kernel(const float* __restrict__ x,
                        const float* __restrict__ W_in,
                        const float* __restrict__ b_in,
                        const float* __restrict__ W_att,
                        const float* __restrict__ b_att,
                        const float* __restrict__ gamma,
                        const float* __restrict__ beta,
                        const float* __restrict__ W_c,
                        const float* __restrict__ b_c,
                        float* __restrict__ out)
{
    extern __shared__ char smem[];
    const uint32_t sb = smem_u32(smem);
    float* part = (float*)(smem + O_PART);
    float* fin  = (float*)(smem + O_FIN);
    float* lns  = (float*)(smem + O_LN);
    float* vec  = (float*)(smem + O_VEC);

    const int tid  = threadIdx.x;
    const int wid  = tid >> 5, lane = tid & 31;
    const int base = blockIdx.x * M_ROWS;
    const int gq = wid & 3;              // m-row group
    const int m0 = gq * 32;
    const int n0 = (wid >> 2) * 32;
    const int wc = wid >> 2;
    const int tg = (wc << 5) + lane;     // thread index within the 128-thread group

    // A: non-trans ldmatrix offsets
    const uint32_t aOff = (uint32_t)(m0 + (lane & 15)) * SBB + ((uint32_t)(lane >> 4) << 4);
    // W (k-major) trans ldmatrix offsets: lane groups of 8 give rows of k;
    // groups 0/1 -> k-halves of n0..n0+7, groups 2/3 -> k-halves of n0+8..n0+15
    const uint32_t bOffT = (uint32_t)(((lane >> 3) & 1) * 8 + (lane & 7)) * SBW
                         + ((uint32_t)(n0 + ((lane >> 4) << 3)) << 1);

    const int rBase = m0 + (lane >> 2);
    const int cBase = n0 + (lane & 3) * 2;

    const float invf[KT] = {1.0f, 1.0f, 0.5f, 1.6666666667e-1f, 4.1666666667e-2f,
                            8.3333333333e-3f, 1.3888888889e-3f, 1.9841269841e-4f};

    // ---------------- initial staging ----------------
#pragma unroll
    for (int it = 0; it < 16; it++) {
        int idx = tid + it * THREADS;
        int row = idx >> 6, kp = idx & 63;
        float2 v = *(const float2*)(x + (size_t)(base + row) * H + 2 * kp);
        uint32_t hi2, lo2; split2(v.x, v.y, hi2, lo2);
        uint32_t off = (uint32_t)row * SBB + (uint32_t)kp * 4;
        *(uint32_t*)(smem + O_AHI + off) = hi2;
        *(uint32_t*)(smem + O_ALO + off) = lo2;
    }
    stage_w(smem, W_in, tid);
    if (tid < 128) vec[VF_BIAS + tid] = b_in[tid];
    for (int i = tid; i < 3 * 128; i += THREADS) {
        vec[VF_BIAS + 128 + i] = b_att[i];
        vec[VF_G + i]  = gamma[i];
        vec[VF_BE + i] = beta[i];
    }
    for (int i = tid; i < H * NC; i += THREADS) vec[VF_WC + i] = W_c[i];
    if (tid < NC) vec[VF_BC + tid] = b_c[tid];
    __syncthreads();

    float d[2][4][4];

    // ---------------- in-proj GEMM + epilogue ----------------
    mma_gemm(sb, aOff, bOffT, d);
    __syncthreads();
    stage_w(smem, W_att, tid);
    {
        const float* sBias = vec + VF_BIAS;
#pragma unroll
        for (int mi = 0; mi < 2; mi++)
#pragma unroll
        for (int ri = 0; ri < 2; ri++) {
            int row = rBase + mi * 16 + ri * 8;
#pragma unroll
            for (int na = 0; na < 4; na++) {
                int col = cBase + na * 8;
                float v0 = d[mi][na][2 * ri]     + sBias[col];
                float v1 = d[mi][na][2 * ri + 1] + sBias[col + 1];
                uint32_t hi2, lo2; split2(v0, v1, hi2, lo2);
                uint32_t off = (uint32_t)row * SBB + (uint32_t)col * 2;
                *(uint32_t*)(smem + O_AHI + off) = hi2;
                *(uint32_t*)(smem + O_ALO + off) = lo2;
            }
        }
    }
    __syncthreads();

    // ---------------- attention layers ----------------
    for (int l = 0; l < NATT; l++) {
        const bool lastl = (l == NATT - 1);
        mma_gemm(sb, aOff, bOffT, d);
        __syncthreads();
        if (!lastl) stage_w(smem, W_att + (size_t)(l + 1) * H * H, tid);

        const float* sBias = vec + VF_BIAS + 128 + l * 128;
        const float* sG    = vec + VF_G + l * 128;
        const float* sBe   = vec + VF_BE + l * 128;

        // ---- pass A: u = tanh(D+b); moments; quad-shfl; part (own rows) ----
#pragma unroll
        for (int mi = 0; mi < 2; mi++)
#pragma unroll
        for (int ri = 0; ri < 2; ri++) {
            int row = rBase + mi * 16 + ri * 8;
            ull sm2[KT2], mm2[KT2];
#pragma unroll
            for (int p = 0; p < KT2; p++) { sm2[p] = 0ull; mm2[p] = 0ull; }
#pragma unroll
            for (int na = 0; na < 4; na++) {
                int col = cBase + na * 8;
                float u0 = fast_tanh(d[mi][na][2 * ri]     + sBias[col]);
                float u1 = fast_tanh(d[mi][na][2 * ri + 1] + sBias[col + 1]);
                d[mi][na][2 * ri]     = u0;
                d[mi][na][2 * ri + 1] = u1;
                uint32_t off = (uint32_t)row * SBB + (uint32_t)col * 2;
                float2 h = join2(*(const uint32_t*)(smem + O_AHI + off),
                                 *(const uint32_t*)(smem + O_ALO + off));
                mom_acc(sm2, mm2, u0, h.x);
                mom_acc(sm2, mm2, u1, h.y);
            }
            float v16[16];
#pragma unroll
            for (int p = 0; p < KT2; p++) {
                unpack2(sm2[p], v16[2 * p], v16[2 * p + 1]);
                unpack2(mm2[p], v16[8 + 2 * p], v16[8 + 2 * p + 1]);
            }
#pragma unroll
            for (int k = 0; k < 16; k++) {
                v16[k] += __shfl_xor_sync(0xffffffffu, v16[k], 1);
                v16[k] += __shfl_xor_sync(0xffffffffu, v16[k], 2);
            }
            int j = lane & 3;
            *(float4*)&part[row * PART_STRIDE + wc * 16 + j * 4] =
                make_float4(v16[j * 4], v16[j * 4 + 1], v16[j * 4 + 2], v16[j * 4 + 3]);
        }
        BARG(gq);

        // ---- group reduce: sum partials over the 4 col-warps (own rows) ----
        {
            int row = m0 + (tg >> 2), j = tg & 3;
            float4 s = *(const float4*)&part[row * PART_STRIDE + 0 * 16 + j * 4];
#pragma unroll
            for (int q = 1; q < 4; q++) {
                float4 t = *(const float4*)&part[row * PART_STRIDE + q * 16 + j * 4];
                s.x += t.x; s.y += t.y; s.z += t.z; s.w += t.w;
            }
            *(float4*)&fin[row * FIN_STRIDE + j * 4] = s;
        }
        BARG(gq);

        // ---- pass B: Horner out, z in regs, LN partials ----
#pragma unroll
        for (int mi = 0; mi < 2; mi++)
#pragma unroll
        for (int ri = 0; ri < 2; ri++) {
            int row = rBase + mi * 16 + ri * 8;
            float4 f0 = *(const float4*)&fin[row * FIN_STRIDE + 0];
            float4 f1 = *(const float4*)&fin[row * FIN_STRIDE + 4];
            float4 f2 = *(const float4*)&fin[row * FIN_STRIDE + 8];
            float4 f3 = *(const float4*)&fin[row * FIN_STRIDE + 12];
            float smv[8] = {f0.x, f0.y, f0.z, f0.w, f1.x, f1.y, f1.z, f1.w};
            float mmv[8] = {f2.x, f2.y, f2.z, f2.w, f3.x, f3.y, f3.z, f3.w};
            ull pm[KT];
#pragma unroll
            for (int k = 0; k < KT; k++) pm[k] = pack2(mmv[k] * invf[k], smv[k] * invf[k]);

            float lsum = 0.f, lsq = 0.f;
#pragma unroll
            for (int na = 0; na < 4; na++) {
                int col = cBase + na * 8;
                uint32_t off = (uint32_t)row * SBB + (uint32_t)col * 2;
                float2 h = join2(*(const uint32_t*)(smem + O_AHI + off),
                                 *(const uint32_t*)(smem + O_ALO + off));
#pragma unroll
                for (int ci = 0; ci < 2; ci++) {
                    float u = d[mi][na][2 * ri + ci];
                    ull u2 = pack2(u, u);
                    ull nd = pm[KT - 1];
#pragma unroll
                    for (int k = KT - 2; k >= 0; k--) nd = fma2(nd, u2, pm[k]);
                    float num, den; unpack2(nd, num, den);
                    float z = (ci ? h.y : h.x) + __fdividef(num, den);
                    d[mi][na][2 * ri + ci] = z;
                    lsum += z;
                    lsq = fmaf(z, z, lsq);
                }
            }
            lsum += __shfl_xor_sync(0xffffffffu, lsum, 1);
            lsum += __shfl_xor_sync(0xffffffffu, lsum, 2);
            lsq  += __shfl_xor_sync(0xffffffffu, lsq, 1);
            lsq  += __shfl_xor_sync(0xffffffffu, lsq, 2);
            if ((lane & 3) == 0)
                *(float2*)&lns[row * LN_STRIDE + wc * 2] = make_float2(lsum, lsq);
        }
        BARG(gq);

        // ---- pass C: LN apply -> A tiles, or fused classifier ----
        if (!lastl) {
#pragma unroll
            for (int mi = 0; mi < 2; mi++)
#pragma unroll
            for (int ri = 0; ri < 2; ri++) {
                int row = rBase + mi * 16 + ri * 8;
                float tsum = 0.f, tsq = 0.f;
#pragma unroll
                for (int q = 0; q < 4; q++) {
                    float2 t = *(const float2*)&lns[row * LN_STRIDE + q * 2];
                    tsum += t.x; tsq += t.y;
                }
                float mu   = tsum * (1.f / H);
                float var  = tsq * (1.f / H) - mu * mu;
                float rinv = rsqrtf(var + EPS_LN);
#pragma unroll
                for (int na = 0; na < 4; na++) {
                    int col = cBase + na * 8;
                    float hn0 = fmaf((d[mi][na][2 * ri]     - mu) * rinv, sG[col],     sBe[col]);
                    float hn1 = fmaf((d[mi][na][2 * ri + 1] - mu) * rinv, sG[col + 1], sBe[col + 1]);
                    uint32_t hi2, lo2; split2(hn0, hn1, hi2, lo2);
                    uint32_t off = (uint32_t)row * SBB + (uint32_t)col * 2;
                    *(uint32_t*)(smem + O_AHI + off) = hi2;
                    *(uint32_t*)(smem + O_ALO + off) = lo2;
                }
            }
            __syncthreads();   // A fully written + stage_w complete -> next GEMM
        } else {
            const float* sWc = vec + VF_WC;
#pragma unroll
            for (int mi = 0; mi < 2; mi++)
#pragma unroll
            for (int ri = 0; ri < 2; ri++) {
                int row = rBase + mi * 16 + ri * 8;
                float tsum = 0.f, tsq = 0.f;
#pragma unroll
                for (int q = 0; q < 4; q++) {
                    float2 t = *(const float2*)&lns[row * LN_STRIDE + q * 2];
                    tsum += t.x; tsq += t.y;
                }
                float mu   = tsum * (1.f / H);
                float var  = tsq * (1.f / H) - mu * mu;
                float rinv = rsqrtf(var + EPS_LN);
                float acc[NC];
#pragma unroll
                for (int c = 0; c < NC; c++) acc[c] = 0.f;
#pragma unroll
                for (int na = 0; na < 4; na++) {
                    int col = cBase + na * 8;
                    float hn0 = fmaf((d[mi][na][2 * ri]     - mu) * rinv, sG[col],     sBe[col]);
                    float hn1 = fmaf((d[mi][na][2 * ri + 1] - mu) * rinv, sG[col + 1], sBe[col + 1]);
#pragma unroll
                    for (int c = 0; c < NC; c++)
                        acc[c] += hn0 * sWc[col * NC + c] + hn1 * sWc[(col + 1) * NC + c];
                }
#pragma unroll
                for (int c = 0; c < NC; c++) {
                    acc[c] += __shfl_xor_sync(0xffffffffu, acc[c], 1);
                    acc[c] += __shfl_xor_sync(0xffffffffu, acc[c], 2);
                }
                if ((lane & 3) == 0) {
                    float* p = &part[row * PART_STRIDE + wc * 10];
#pragma unroll
                    for (int c = 0; c < NC; c += 2)
                        *(float2*)&p[c] = make_float2(acc[c], acc[c + 1]);
                }
            }
            BARG(gq);
            // warp w (w<4) is in group w and reads rows 32w..32w+31 = its own group's part
            if (tid < 128) {
                float o[NC];
#pragma unroll
                for (int c = 0; c < NC; c++) o[c] = vec[VF_BC + c];
#pragma unroll
                for (int q = 0; q < 4; q++)
#pragma unroll
                    for (int c = 0; c < NC; c++)
                        o[c] += part[tid * PART_STRIDE + q * 10 + c];
                float* og = out + (size_t)(base + tid) * NC;
#pragma unroll
                for (int c = 0; c < NC; c += 2)
                    *(float2*)&og[c] = make_float2(o[c], o[c + 1]);
            }
        }
    }
}

extern "C" void kernel_launch(void* const* d_in, const int* in_sizes, int n_in,
                              void* d_out, int out_size)
{
    const float* x     = (const float*)d_in[0];
    const float* W_in  = (const float*)d_in[1];
    const float* b_in  = (const float*)d_in[2];
    const float* W_att = (const float*)d_in[3];
    const float* b_att = (const float*)d_in[4];
    const float* gam   = (const float*)d_in[5];
    const float* bet   = (const float*)d_in[6];
    const float* W_c   = (const float*)d_in[7];
    const float* b_c   = (const float*)d_in[8];

    cudaFuncSetAttribute(simple_attention_kernel,
                         cudaFuncAttributeMaxDynamicSharedMemorySize, SMEM_TOTAL);

    simple_attention_kernel<<<B_TOTAL / M_ROWS, THREADS, SMEM_TOTAL>>>(
        x, W_in, b_in, W_att, b_att, gam, bet, W_c, b_c, (float*)d_out);
}